// round 1
// baseline (speedup 1.0000x reference)
#include <cuda_runtime.h>
#include <math.h>

#define NB 256   // batch
#define NL 128   // seq len
#define NC 256   // input channels
#define NH 512   // hidden
#define NG 2048  // 4*H

// ---------------- scratch (device globals; no allocation allowed) ----------
__device__ float g_Wprime[(size_t)NH * NG];          // Wmh @ Whm          (4 MB)
__device__ float g_Wbig[(size_t)NC * NG];            // Wih + Wmx @ Whm    (2 MB)
__device__ float g_bvec[NG];                         // folded bias
__device__ float g_P[(size_t)NL * NB * NG];          // [l][b][4H] precomputed input term (268 MB)
__device__ float g_h[2][(size_t)NB * NH];            // ping-pong hidden state
__device__ float g_Cst[(size_t)NB * NH];             // cell state (elementwise-owned, in-place ok)

// ---------------- init ------------------------------------------------------
__global__ void init_state_kernel() {
    int i = blockIdx.x * blockDim.x + threadIdx.x;
    if (i < NB * NH) { g_h[0][i] = 0.f; g_Cst[i] = 0.f; }
}

// ---------------- folded bias: bvec = bih + bhm + (bmx+bmh) @ Whm -----------
__global__ void bvec_kernel(const float* __restrict__ bih, const float* __restrict__ bhm,
                            const float* __restrict__ bmx, const float* __restrict__ bmh,
                            const float* __restrict__ Whm) {
    int n = blockIdx.x * blockDim.x + threadIdx.x;   // 0..2047
    float s = bih[n] + bhm[n];
    for (int k = 0; k < NH; k++)
        s = fmaf(bmx[k] + bmh[k], Whm[(size_t)k * NG + n], s);
    g_bvec[n] = s;
}

// ---------------- generic fp32 tiled GEMM: Out = A@B (+Cadd) (+bias) --------
// BM=BN=64, BK=16, 256 threads, 4x4 microtile. Dims must divide tiles (they do).
// SWIZ: output row m = b*NL + l is written to row l*NB + b  (gives [l][b][:] layout for P)
template <bool SWIZ, bool HASC, bool HASB>
__global__ __launch_bounds__(256)
void gemm64(const float* __restrict__ A, const float* __restrict__ Bm,
            const float* __restrict__ Cadd, const float* __restrict__ bias,
            float* __restrict__ Out, int M, int N, int K) {
    __shared__ float sA[16][64];
    __shared__ float sB[16][64];
    const int bm = blockIdx.y * 64, bn = blockIdx.x * 64;
    const int tid  = threadIdx.x;
    const int arow = tid >> 2, akq = tid & 3;    // A loader: 64 rows x 4 float4
    const int brow = tid >> 4, bnq = tid & 15;   // B loader: 16 k x 16 float4
    const int tr   = tid >> 4, tcx = tid & 15;   // compute: 16x16 threads, 4x4 each
    float acc[4][4] = {};

    for (int k0 = 0; k0 < K; k0 += 16) {
        float4 av = *reinterpret_cast<const float4*>(A + (size_t)(bm + arow) * K + k0 + akq * 4);
        float4 bv = *reinterpret_cast<const float4*>(Bm + (size_t)(k0 + brow) * N + bn + bnq * 4);
        __syncthreads();
        sA[akq * 4 + 0][arow] = av.x;
        sA[akq * 4 + 1][arow] = av.y;
        sA[akq * 4 + 2][arow] = av.z;
        sA[akq * 4 + 3][arow] = av.w;
        *reinterpret_cast<float4*>(&sB[brow][bnq * 4]) = bv;
        __syncthreads();
#pragma unroll
        for (int k = 0; k < 16; k++) {
            float4 a = *reinterpret_cast<float4*>(&sA[k][tr * 4]);
            float4 b = *reinterpret_cast<float4*>(&sB[k][tcx * 4]);
            float aa[4] = {a.x, a.y, a.z, a.w};
            float bb[4] = {b.x, b.y, b.z, b.w};
#pragma unroll
            for (int i = 0; i < 4; i++)
#pragma unroll
                for (int j = 0; j < 4; j++)
                    acc[i][j] = fmaf(aa[i], bb[j], acc[i][j]);
        }
    }

#pragma unroll
    for (int i = 0; i < 4; i++) {
        int m = bm + tr * 4 + i;
        size_t orow = SWIZ ? ((size_t)(m & (NL - 1)) * NB + (size_t)(m >> 7)) : (size_t)m;
        int n = bn + tcx * 4;
        float4 r = make_float4(acc[i][0], acc[i][1], acc[i][2], acc[i][3]);
        if (HASB) {
            r.x += bias[n]; r.y += bias[n + 1]; r.z += bias[n + 2]; r.w += bias[n + 3];
        }
        if (HASC) {
            float4 c = *reinterpret_cast<const float4*>(Cadd + (size_t)m * N + n);
            r.x += c.x; r.y += c.y; r.z += c.z; r.w += c.w;
        }
        *reinterpret_cast<float4*>(Out + orow * (size_t)N + n) = r;
    }
}

// ---------------- x_tilde: alpha = softmax_c(x^T Wa_x + ba); out = alpha*x --
__global__ void xtilde_kernel(const float* __restrict__ x, const float* __restrict__ Wa,
                              const float* __restrict__ ba, float* __restrict__ out) {
    __shared__ float red[NC];
    __shared__ float s_wa[NL];
    int b = blockIdx.x, c = threadIdx.x;   // 256 threads == NC
    if (c < NL) s_wa[c] = Wa[2 * NH + c];
    __syncthreads();
    const float* xb = x + (size_t)b * NL * NC;
    float s = ba[0];
    for (int l = 0; l < NL; l++) s = fmaf(xb[(size_t)l * NC + c], s_wa[l], s);
    red[c] = s; __syncthreads();
    for (int o = NC / 2; o > 0; o >>= 1) { if (c < o) red[c] = fmaxf(red[c], red[c + o]); __syncthreads(); }
    float mx = red[0]; __syncthreads();
    float e = expf(s - mx);
    red[c] = e; __syncthreads();
    for (int o = NC / 2; o > 0; o >>= 1) { if (c < o) red[c] += red[c + o]; __syncthreads(); }
    float alpha = e / red[0];
    float* ob = out + (size_t)b * NL * NC;
    for (int l = 0; l < NL; l++) ob[(size_t)l * NC + c] = alpha * xb[(size_t)l * NC + c];
}

// ---------------- recurrent step: gates = P_t + h @ W'; LSTM pointwise ------
// grid (16,8): 16 h-col tiles of 32, 8 batch-row tiles of 32. 256 threads.
// Each block: 32 rows x 32 hcols x 4 gates (=32x128 GEMM tile), K=512.
__global__ __launch_bounds__(256)
void step_kernel(int t, int par, float* __restrict__ out) {
    __shared__ float smem[32 * 128];          // 16 KB, overlaid
    float* sH = smem;                         // [16][32]  (k-major, transposed h tile)
    float* sW = smem + 512;                   // [16][128] (col = gate*32 + hcol_local)
    const int hc0 = blockIdx.x * 32;
    const int r0  = blockIdx.y * 32;
    const int tid = threadIdx.x;
    const float* hsrc = g_h[par];
    const int tr = tid >> 5;                  // 0..7  -> rows tr*4..tr*4+3
    const int tc = tid & 31;                  // gate = tc>>3, hcol base = (tc&7)*4
    float acc[4][4] = {};

    for (int k0 = 0; k0 < NH; k0 += 16) {
        int q1 = tid, q2 = tid + 256;         // 512 float4 of W' tile
        float4 wv0 = *reinterpret_cast<const float4*>(
            &g_Wprime[(size_t)(k0 + (q1 >> 5)) * NG + ((q1 & 31) >> 3) * NH + hc0 + (q1 & 7) * 4]);
        float4 wv1 = *reinterpret_cast<const float4*>(
            &g_Wprime[(size_t)(k0 + (q2 >> 5)) * NG + ((q2 & 31) >> 3) * NH + hc0 + (q2 & 7) * 4]);
        float4 hv = make_float4(0.f, 0.f, 0.f, 0.f);
        if (tid < 128) {
            int r = tid >> 2, kq = tid & 3;
            hv = *reinterpret_cast<const float4*>(&hsrc[(size_t)(r0 + r) * NH + k0 + kq * 4]);
        }
        __syncthreads();
        *reinterpret_cast<float4*>(&sW[(q1 >> 5) * 128 + (q1 & 31) * 4]) = wv0;
        *reinterpret_cast<float4*>(&sW[(q2 >> 5) * 128 + (q2 & 31) * 4]) = wv1;
        if (tid < 128) {
            int r = tid >> 2, kq = tid & 3;
            sH[(kq * 4 + 0) * 32 + r] = hv.x;
            sH[(kq * 4 + 1) * 32 + r] = hv.y;
            sH[(kq * 4 + 2) * 32 + r] = hv.z;
            sH[(kq * 4 + 3) * 32 + r] = hv.w;
        }
        __syncthreads();
#pragma unroll
        for (int k = 0; k < 16; k++) {
            float4 a = *reinterpret_cast<float4*>(&sH[k * 32 + tr * 4]);
            float4 w = *reinterpret_cast<float4*>(&sW[k * 128 + tc * 4]);
            float aa[4] = {a.x, a.y, a.z, a.w};
            float ww[4] = {w.x, w.y, w.z, w.w};
#pragma unroll
            for (int i = 0; i < 4; i++)
#pragma unroll
                for (int j = 0; j < 4; j++)
                    acc[i][j] = fmaf(aa[i], ww[j], acc[i][j]);
        }
    }
    __syncthreads();

    // stash gate partial sums: sG[row][gate*32 + hcol], 32x128
    float* sG = smem;
#pragma unroll
    for (int i = 0; i < 4; i++)
        *reinterpret_cast<float4*>(&sG[(tr * 4 + i) * 128 + tc * 4]) =
            make_float4(acc[i][0], acc[i][1], acc[i][2], acc[i][3]);
    __syncthreads();

    const float* Pt = g_P + (size_t)t * NB * NG;
#pragma unroll
    for (int e = 0; e < 4; e++) {
        int idx = tid + e * 256;              // 0..1023
        int row = idx >> 5, j = idx & 31;
        int b = r0 + row, hj = hc0 + j;
        const float* pr = Pt + (size_t)b * NG;
        float iv = sG[row * 128 +       j] + pr[hj];
        float fv = sG[row * 128 +  32 + j] + pr[NH + hj];
        float gv = sG[row * 128 +  64 + j] + pr[2 * NH + hj];
        float ov = sG[row * 128 +  96 + j] + pr[3 * NH + hj];
        float si = 1.f / (1.f + expf(-iv));
        float sf = 1.f / (1.f + expf(-fv));
        float so = 1.f / (1.f + expf(-ov));
        float tg = tanhf(gv);
        size_t sidx = (size_t)b * NH + hj;
        float Cn = sf * g_Cst[sidx] + si * tg;
        float hn = so * tanhf(Cn);
        g_Cst[sidx] = Cn;
        g_h[par ^ 1][sidx] = hn;
        size_t o1 = (size_t)b * (NL * NH) + (size_t)t * NH + hj;
        out[o1] = hn;                                   // hidden_seq
        out[(size_t)NB * NL * NH + o1] = Cn;            // c_seq
    }
}

// ---------------- host ------------------------------------------------------
extern "C" void kernel_launch(void* const* d_in, const int* in_sizes, int n_in,
                              void* d_out, int out_size) {
    const float* x   = (const float*)d_in[0];
    const float* Wih = (const float*)d_in[1];
    const float* bih = (const float*)d_in[2];
    const float* Wmx = (const float*)d_in[3];
    const float* bmx = (const float*)d_in[4];
    const float* Wmh = (const float*)d_in[5];
    const float* bmh = (const float*)d_in[6];
    const float* Whm = (const float*)d_in[7];
    const float* bhm = (const float*)d_in[8];
    const float* Wa  = (const float*)d_in[9];
    const float* ba  = (const float*)d_in[10];
    float* out = (float*)d_out;

    float *pWp, *pWb, *pBv, *pP;
    cudaGetSymbolAddress((void**)&pWp, g_Wprime);
    cudaGetSymbolAddress((void**)&pWb, g_Wbig);
    cudaGetSymbolAddress((void**)&pBv, g_bvec);
    cudaGetSymbolAddress((void**)&pP,  g_P);

    init_state_kernel<<<(NB * NH + 255) / 256, 256>>>();

    // W' = Wmh @ Whm                         (512 x 2048, K=512)
    gemm64<false, false, false><<<dim3(NG / 64, NH / 64), 256>>>(
        Wmh, Whm, nullptr, nullptr, pWp, NH, NG, NH);
    // Wbig = Wih + Wmx @ Whm                 (256 x 2048, K=512)
    gemm64<false, true, false><<<dim3(NG / 64, NC / 64), 256>>>(
        Wmx, Whm, Wih, nullptr, pWb, NC, NG, NH);
    // bvec
    bvec_kernel<<<NG / 256, 256>>>(bih, bhm, bmx, bmh, Whm);
    // P[l][b][:] = x2d @ Wbig + bvec         (32768 x 2048, K=256)
    gemm64<true, false, true><<<dim3(NG / 64, (NB * NL) / 64), 256>>>(
        x, pWb, nullptr, pBv, pP, NB * NL, NG, NC);
    // x_tilde (alpha is time-invariant: softmax is shift-invariant per row)
    xtilde_kernel<<<NB, 256>>>(x, Wa, ba, out + (size_t)2 * NB * NL * NH);

    // sequential scan: 1 fused GEMM+LSTM kernel per step
    for (int t = 0; t < NL; t++)
        step_kernel<<<dim3(16, 8), 256>>>(t, t & 1, out);
}

// round 3
// speedup vs baseline: 1.1933x; 1.1933x over previous
#include <cuda_runtime.h>
#include <cuda_bf16.h>
#include <math.h>
#include <stdint.h>

#define NB 256   // batch
#define NL 128   // seq len
#define NC 256   // input channels
#define NH 512   // hidden
#define NG 2048  // 4*H

__device__ __forceinline__ uint32_t smem_u32_of(const void* p) {
    uint32_t a;
    asm("{ .reg .u64 t; cvta.to.shared.u64 t, %1; cvt.u32.u64 %0, t; }" : "=r"(a) : "l"(p));
    return a;
}

// ===================== device globals (no allocation allowed) ===============
__device__ float g_Wp[(size_t)NH * NG];               // W' = Wmh@Whm (fp32)
__device__ float g_Wb[(size_t)NC * NG];               // Wbig = Wih + Wmx@Whm
__device__ float g_bvp[NG];                           // folded bias, permuted cols
__device__ __nv_bfloat16 g_Wpcat[(size_t)NG * (3 * NH)];  // [n' perm][1536] = [hi|lo|hi]
__device__ __nv_bfloat16 g_Wbcat[(size_t)NG * (3 * NC)];  // [n' perm][768]
__device__ __nv_bfloat16 g_xcat[(size_t)NB * NL * (3 * NC)]; // [m][768] = [hi|hi|lo]
__device__ __nv_bfloat16 g_hcat[2][(size_t)NB * (3 * NH)];   // [b][1536] = [hi|hi|lo]
__device__ float g_P[(size_t)NB * NL * NG];           // x@Wbig + bias, permuted cols
__device__ float g_Cst[(size_t)NB * NH];              // cell state

// ===================== prep kernels =========================================
__global__ void init_state_kernel() {
    int i = blockIdx.x * blockDim.x + threadIdx.x;
    if (i < NB * (3 * NH)) g_hcat[0][i] = __float2bfloat16_rn(0.f);
    if (i < NB * NH) g_Cst[i] = 0.f;
}

__device__ __forceinline__ int perm_col(int n) {       // natural gate col -> permuted
    int j = n & 511, g = n >> 9;
    return ((j >> 3) << 5) | (g << 3) | (j & 7);
}

__global__ void bvec_kernel(const float* __restrict__ bih, const float* __restrict__ bhm,
                            const float* __restrict__ bmx, const float* __restrict__ bmh,
                            const float* __restrict__ Whm) {
    int n = blockIdx.x * blockDim.x + threadIdx.x;
    float s = bih[n] + bhm[n];
    for (int k = 0; k < NH; k++)
        s = fmaf(bmx[k] + bmh[k], Whm[(size_t)k * NG + n], s);
    g_bvp[perm_col(n)] = s;
}

// fp32 SIMT GEMM for small weight prep
template <bool HASC>
__global__ __launch_bounds__(256)
void gemm64(const float* __restrict__ A, const float* __restrict__ Bm,
            const float* __restrict__ Cadd, float* __restrict__ Out,
            int M, int N, int K) {
    __shared__ float sA[16][64];
    __shared__ float sB[16][64];
    const int bm = blockIdx.y * 64, bn = blockIdx.x * 64;
    const int tid  = threadIdx.x;
    const int arow = tid >> 2, akq = tid & 3;
    const int brow = tid >> 4, bnq = tid & 15;
    const int tr   = tid >> 4, tcx = tid & 15;
    float acc[4][4] = {};
    for (int k0 = 0; k0 < K; k0 += 16) {
        float4 av = *reinterpret_cast<const float4*>(A + (size_t)(bm + arow) * K + k0 + akq * 4);
        float4 bv = *reinterpret_cast<const float4*>(Bm + (size_t)(k0 + brow) * N + bn + bnq * 4);
        __syncthreads();
        sA[akq * 4 + 0][arow] = av.x; sA[akq * 4 + 1][arow] = av.y;
        sA[akq * 4 + 2][arow] = av.z; sA[akq * 4 + 3][arow] = av.w;
        *reinterpret_cast<float4*>(&sB[brow][bnq * 4]) = bv;
        __syncthreads();
#pragma unroll
        for (int k = 0; k < 16; k++) {
            float4 a = *reinterpret_cast<float4*>(&sA[k][tr * 4]);
            float4 b = *reinterpret_cast<float4*>(&sB[k][tcx * 4]);
            float aa[4] = {a.x, a.y, a.z, a.w};
            float bb[4] = {b.x, b.y, b.z, b.w};
#pragma unroll
            for (int i = 0; i < 4; i++)
#pragma unroll
                for (int j = 0; j < 4; j++)
                    acc[i][j] = fmaf(aa[i], bb[j], acc[i][j]);
        }
    }
#pragma unroll
    for (int i = 0; i < 4; i++) {
        int m = bm + tr * 4 + i, n = bn + tcx * 4;
        float4 r = make_float4(acc[i][0], acc[i][1], acc[i][2], acc[i][3]);
        if (HASC) {
            float4 c = *reinterpret_cast<const float4*>(Cadd + (size_t)m * N + n);
            r.x += c.x; r.y += c.y; r.z += c.z; r.w += c.w;
        }
        *reinterpret_cast<float4*>(Out + (size_t)m * N + n) = r;
    }
}

// transpose + permute + hi/lo split -> weight concat [2048 perm][3K] = [hi|lo|hi]
__global__ void tsplit_kernel(const float* __restrict__ src, int K,
                              __nv_bfloat16* __restrict__ out) {
    __shared__ float sA[32][33];
    const int n0 = blockIdx.x * 32, k0 = blockIdx.y * 32;
    const int t = threadIdx.x;
    {
        int nl = t & 31, rr = t >> 5;
#pragma unroll
        for (int it = 0; it < 4; it++) {
            int kl = it * 8 + rr;
            sA[kl][nl] = src[(size_t)(k0 + kl) * NG + n0 + nl];
        }
    }
    __syncthreads();
    int nlo = t >> 3, ks = t & 7;
    int np = perm_col(n0 + nlo);
    union { __nv_bfloat16 b[4]; uint2 u; } H, L;
#pragma unroll
    for (int kk = 0; kk < 4; kk++) {
        float v = sA[ks * 4 + kk][nlo];
        H.b[kk] = __float2bfloat16_rn(v);
        L.b[kk] = __float2bfloat16_rn(v - __bfloat162float(H.b[kk]));
    }
    size_t base = (size_t)np * (3 * K) + k0 + ks * 4;
    *reinterpret_cast<uint2*>(out + base)         = H.u;
    *reinterpret_cast<uint2*>(out + base + K)     = L.u;
    *reinterpret_cast<uint2*>(out + base + 2 * K) = H.u;
}

// x fp32 [m][256] -> xcat bf16 [m][768] = [hi|hi|lo]
__global__ void xsplit_kernel(const float* __restrict__ x) {
    size_t i = (size_t)blockIdx.x * blockDim.x + threadIdx.x;  // float4 index
    float4 v = reinterpret_cast<const float4*>(x)[i];
    float f[4] = {v.x, v.y, v.z, v.w};
    union { __nv_bfloat16 b[4]; uint2 u; } H, L;
#pragma unroll
    for (int k = 0; k < 4; k++) {
        H.b[k] = __float2bfloat16_rn(f[k]);
        L.b[k] = __float2bfloat16_rn(f[k] - __bfloat162float(H.b[k]));
    }
    size_t m = i >> 6, c = (i & 63) * 4;
    __nv_bfloat16* row = g_xcat + m * (3 * NC) + c;
    *reinterpret_cast<uint2*>(row)            = H.u;
    *reinterpret_cast<uint2*>(row + NC)       = H.u;
    *reinterpret_cast<uint2*>(row + 2 * NC)   = L.u;
}

// ===================== HMMA bf16 GEMM (mma.sync m16n8k16) ===================
// C[M][2048 perm] = A[M][Kc] @ Bw[2048 perm][Kc]^T    (both K-major, bf16)
// EPI=0: += bias(g_bvp), store to g_P.  EPI=1: fused LSTM pointwise epilogue.
template <int BM, int BN, int WM_, int WN_, int EPI>
__global__ __launch_bounds__(32 * WM_ * WN_)
void gemm_mma(const __nv_bfloat16* __restrict__ A,
              const __nv_bfloat16* __restrict__ Bw, int Kc,
              int t, int par, float* __restrict__ out) {
    constexpr int NT = 32 * WM_ * WN_;
    constexpr int WM = BM / WM_;
    constexpr int MF = WM / 16;
    static_assert(BN == WN_ * 32, "warp n-tile must be 32");
    __shared__ __nv_bfloat16 sA[2][BM][40];
    __shared__ __nv_bfloat16 sB[2][BN][40];

    const int tid = threadIdx.x, lane = tid & 31, w = tid >> 5;
    const int wn0 = (w % WN_) * 32, wm0 = (w / WN_) * WM;
    const int m0 = blockIdx.y * BM, n0 = blockIdx.x * BN;

    auto load_stage = [&](int s, int k0) {
        constexpr int CH = (BM + BN) * 4;
#pragma unroll
        for (int i = 0; i < CH / NT; i++) {
            int q = i * NT + tid;
            const __nv_bfloat16* src;
            uint32_t dst;
            if (q < BM * 4) {
                int r = q >> 2, c = q & 3;
                src = A + (size_t)(m0 + r) * Kc + k0 + c * 8;
                dst = smem_u32_of(&sA[s][r][c * 8]);
            } else {
                int q2 = q - BM * 4, r = q2 >> 2, c = q2 & 3;
                src = Bw + (size_t)(n0 + r) * Kc + k0 + c * 8;
                dst = smem_u32_of(&sB[s][r][c * 8]);
            }
            asm volatile("cp.async.cg.shared.global [%0], [%1], 16;" :: "r"(dst), "l"(src));
        }
        asm volatile("cp.async.commit_group;");
    };

    float acc[MF][4][4] = {};
    const int arow = (lane & 7) + ((lane >> 3) & 1) * 8;
    const int akm  = (lane >> 4) & 1;
    const int brow = lane & 7;
    const int bkm  = (lane >> 3) & 1;

    auto compute_stage = [&](int s) {
#pragma unroll
        for (int ks = 0; ks < 2; ks++) {
            uint32_t aR[MF][4], bR[4][2];
#pragma unroll
            for (int ni = 0; ni < 4; ni++) {
                uint32_t ad = smem_u32_of(&sB[s][wn0 + ni * 8 + brow][ks * 16 + bkm * 8]);
                asm volatile("ldmatrix.sync.aligned.m8n8.x2.shared.b16 {%0,%1}, [%2];"
                             : "=r"(bR[ni][0]), "=r"(bR[ni][1]) : "r"(ad));
            }
#pragma unroll
            for (int mi = 0; mi < MF; mi++) {
                uint32_t ad = smem_u32_of(&sA[s][wm0 + mi * 16 + arow][ks * 16 + akm * 8]);
                asm volatile("ldmatrix.sync.aligned.m8n8.x4.shared.b16 {%0,%1,%2,%3}, [%4];"
                             : "=r"(aR[mi][0]), "=r"(aR[mi][1]), "=r"(aR[mi][2]), "=r"(aR[mi][3])
                             : "r"(ad));
            }
#pragma unroll
            for (int mi = 0; mi < MF; mi++)
#pragma unroll
                for (int ni = 0; ni < 4; ni++)
                    asm volatile(
                        "mma.sync.aligned.m16n8k16.row.col.f32.bf16.bf16.f32 "
                        "{%0,%1,%2,%3}, {%4,%5,%6,%7}, {%8,%9}, {%0,%1,%2,%3};"
                        : "+f"(acc[mi][ni][0]), "+f"(acc[mi][ni][1]),
                          "+f"(acc[mi][ni][2]), "+f"(acc[mi][ni][3])
                        : "r"(aR[mi][0]), "r"(aR[mi][1]), "r"(aR[mi][2]), "r"(aR[mi][3]),
                          "r"(bR[ni][0]), "r"(bR[ni][1]));
        }
    };

    const int NIT = Kc >> 5;
    load_stage(0, 0);
    for (int it = 0; it < NIT; it++) {
        if (it + 1 < NIT) {
            load_stage((it + 1) & 1, (it + 1) * 32);
            asm volatile("cp.async.wait_group 1;");
        } else {
            asm volatile("cp.async.wait_group 0;");
        }
        __syncthreads();
        compute_stage(it & 1);
        __syncthreads();
    }

    if (EPI == 0) {
        // P = acc + bias (permuted layout)
#pragma unroll
        for (int mi = 0; mi < MF; mi++) {
            int r = m0 + wm0 + mi * 16 + (lane >> 2);
#pragma unroll
            for (int ni = 0; ni < 4; ni++) {
                int col = n0 + wn0 + ni * 8 + (lane & 3) * 2;
                float b0 = g_bvp[col], b1 = g_bvp[col + 1];
                *reinterpret_cast<float2*>(&g_P[(size_t)r * NG + col]) =
                    make_float2(acc[mi][ni][0] + b0, acc[mi][ni][1] + b1);
                *reinterpret_cast<float2*>(&g_P[(size_t)(r + 8) * NG + col]) =
                    make_float2(acc[mi][ni][2] + b0, acc[mi][ni][3] + b1);
            }
        }
    } else {
        // fused LSTM pointwise: gates = acc + P_t ; update C, h; emit outputs
        const int uhi = (n0 + wn0) >> 5;
        const int p0 = (lane & 3) * 2;
        __nv_bfloat16* hdst = g_hcat[par ^ 1];
#pragma unroll
        for (int mi = 0; mi < MF; mi++) {
#pragma unroll
            for (int half = 0; half < 2; half++) {
                int b = m0 + wm0 + mi * 16 + (lane >> 2) + half * 8;   // batch row
                const float* Pr = g_P + ((size_t)b * NL + t) * NG;
#pragma unroll
                for (int e = 0; e < 2; e++) {
                    int j = uhi * 8 + p0 + e;                 // hidden unit
                    int nn = n0 + wn0 + p0 + e;               // permuted col, gate 0
                    int a = half * 2 + e;
                    float iv = acc[mi][0][a] + Pr[nn];
                    float fv = acc[mi][1][a] + Pr[nn + 8];
                    float gv = acc[mi][2][a] + Pr[nn + 16];
                    float ov = acc[mi][3][a] + Pr[nn + 24];
                    float si = 1.f / (1.f + expf(-iv));
                    float sf = 1.f / (1.f + expf(-fv));
                    float so = 1.f / (1.f + expf(-ov));
                    float tg = tanhf(gv);
                    size_t cidx = (size_t)b * NH + j;
                    float Cn = sf * g_Cst[cidx] + si * tg;
                    float hn = so * tanhf(Cn);
                    g_Cst[cidx] = Cn;
                    size_t o = (size_t)b * (NL * NH) + (size_t)t * NH + j;
                    out[o] = hn;
                    out[o + (size_t)NB * NL * NH] = Cn;
                    __nv_bfloat16 hh = __float2bfloat16_rn(hn);
                    __nv_bfloat16 hl = __float2bfloat16_rn(hn - __bfloat162float(hh));
                    __nv_bfloat16* hb = hdst + (size_t)b * (3 * NH);
                    hb[j] = hh; hb[j + NH] = hh; hb[j + 2 * NH] = hl;
                }
            }
        }
    }
}

// ===================== x_tilde ==============================================
__global__ void xtilde_kernel(const float* __restrict__ x, const float* __restrict__ Wa,
                              const float* __restrict__ ba, float* __restrict__ out) {
    __shared__ float red[NC];
    __shared__ float s_wa[NL];
    int b = blockIdx.x, c = threadIdx.x;
    if (c < NL) s_wa[c] = Wa[2 * NH + c];
    __syncthreads();
    const float* xb = x + (size_t)b * NL * NC;
    float s = ba[0];
    for (int l = 0; l < NL; l++) s = fmaf(xb[(size_t)l * NC + c], s_wa[l], s);
    red[c] = s; __syncthreads();
    for (int o = NC / 2; o > 0; o >>= 1) { if (c < o) red[c] = fmaxf(red[c], red[c + o]); __syncthreads(); }
    float mx = red[0]; __syncthreads();
    float e = expf(s - mx);
    red[c] = e; __syncthreads();
    for (int o = NC / 2; o > 0; o >>= 1) { if (c < o) red[c] += red[c + o]; __syncthreads(); }
    float alpha = e / red[0];
    float* ob = out + (size_t)b * NL * NC;
    for (int l = 0; l < NL; l++) ob[(size_t)l * NC + c] = alpha * xb[(size_t)l * NC + c];
}

// ===================== host =================================================
extern "C" void kernel_launch(void* const* d_in, const int* in_sizes, int n_in,
                              void* d_out, int out_size) {
    const float* x   = (const float*)d_in[0];
    const float* Wih = (const float*)d_in[1];
    const float* bih = (const float*)d_in[2];
    const float* Wmx = (const float*)d_in[3];
    const float* bmx = (const float*)d_in[4];
    const float* Wmh = (const float*)d_in[5];
    const float* bmh = (const float*)d_in[6];
    const float* Whm = (const float*)d_in[7];
    const float* bhm = (const float*)d_in[8];
    const float* Wa  = (const float*)d_in[9];
    const float* ba  = (const float*)d_in[10];
    float* out = (float*)d_out;

    float *pWp, *pWb;
    __nv_bfloat16 *pWpc, *pWbc, *pXc, *pH0, *pH1;
    cudaGetSymbolAddress((void**)&pWp,  g_Wp);
    cudaGetSymbolAddress((void**)&pWb,  g_Wb);
    cudaGetSymbolAddress((void**)&pWpc, g_Wpcat);
    cudaGetSymbolAddress((void**)&pWbc, g_Wbcat);
    cudaGetSymbolAddress((void**)&pXc,  g_xcat);
    cudaGetSymbolAddress((void**)&pH0,  g_hcat);
    pH1 = pH0 + (size_t)NB * (3 * NH);

    init_state_kernel<<<(NB * 3 * NH + 255) / 256, 256>>>();

    // folded weights (fp32 SIMT — small)
    gemm64<false><<<dim3(NG / 64, NH / 64), 256>>>(Wmh, Whm, nullptr, pWp, NH, NG, NH);
    gemm64<true ><<<dim3(NG / 64, NC / 64), 256>>>(Wmx, Whm, Wih, pWb, NC, NG, NH);
    bvec_kernel<<<NG / 256, 256>>>(bih, bhm, bmx, bmh, Whm);

    // transpose+permute+split to K-concat bf16
    tsplit_kernel<<<dim3(NG / 32, NH / 32), 256>>>(pWp, NH, pWpc);
    tsplit_kernel<<<dim3(NG / 32, NC / 32), 256>>>(pWb, NC, pWbc);
    xsplit_kernel<<<(NB * NL * NC / 4) / 256, 256>>>(x);

    // P = x @ Wbig + bias   (HMMA, Kc = 3*256)
    gemm_mma<128, 128, 2, 4, 0><<<dim3(NG / 128, (NB * NL) / 128), 256>>>(
        pXc, pWbc, 3 * NC, 0, 0, nullptr);

    // x_tilde (softmax over c is time-invariant)
    xtilde_kernel<<<NB, 256>>>(x, Wa, ba, out + (size_t)2 * NB * NL * NH);

    // sequential scan: HMMA GEMM + fused LSTM pointwise per step (Kc = 3*512)
    for (int t = 0; t < NL; t++) {
        const __nv_bfloat16* hsrc = (t & 1) ? pH1 : pH0;
        gemm_mma<64, 64, 2, 2, 1><<<dim3(NG / 64, NB / 64), 128>>>(
            hsrc, pWpc, 3 * NH, t, t & 1, out);
    }
}

// round 5
// speedup vs baseline: 2.2197x; 1.8601x over previous
#include <cuda_runtime.h>
#include <cuda_bf16.h>
#include <math.h>
#include <stdint.h>

#define NB 256   // batch
#define NL 128   // seq len
#define NC 256   // input channels
#define NH 512   // hidden
#define NG 2048  // 4*H

__device__ __forceinline__ uint32_t smem_u32_of(const void* p) {
    uint32_t a;
    asm("{ .reg .u64 t; cvta.to.shared.u64 t, %1; cvt.u32.u64 %0, t; }" : "=r"(a) : "l"(p));
    return a;
}

// ===================== device globals (no allocation allowed) ===============
__device__ float g_Wp[(size_t)NH * NG];               // W' = Wmh@Whm (fp32)
__device__ float g_Wb[(size_t)NC * NG];               // Wbig = Wih + Wmx@Whm
__device__ float g_bvp[NG];                           // folded bias, permuted cols
__device__ __nv_bfloat16 g_Wpcat[(size_t)NG * (3 * NH)];   // [n' perm][1536] = [hi|lo|hi]
__device__ __nv_bfloat16 g_Wbcat[(size_t)NG * (3 * NC)];   // [n' perm][768]
__device__ __nv_bfloat16 g_xcat[(size_t)NB * NL * (3 * NC)]; // [m][768] = [hi|hi|lo]
__device__ __nv_bfloat16 g_hcat[2][(size_t)NB * (3 * NH)];   // [b][1536] = [hi|hi|lo]
__device__ float g_P[(size_t)NL * NB * NG];           // TIME-MAJOR: [t][b][n'] = x@Wbig + bias
__device__ float g_Cst[(size_t)NB * NH];              // cell state
__device__ int   g_bar[4];                            // per-m-group barrier counters

// ===================== prep kernels =========================================
__global__ void init_state_kernel() {
    int i = blockIdx.x * blockDim.x + threadIdx.x;
    if (i < NB * (3 * NH)) g_hcat[0][i] = __float2bfloat16_rn(0.f);
    if (i < NB * NH) g_Cst[i] = 0.f;
    if (i < 4) g_bar[i] = 0;
}

__device__ __forceinline__ int perm_col(int n) {       // natural gate col -> permuted
    int j = n & 511, g = n >> 9;
    return ((j >> 3) << 5) | (g << 3) | (j & 7);
}

__global__ void bvec_kernel(const float* __restrict__ bih, const float* __restrict__ bhm,
                            const float* __restrict__ bmx, const float* __restrict__ bmh,
                            const float* __restrict__ Whm) {
    int n = blockIdx.x * blockDim.x + threadIdx.x;
    float acc[8] = {};
    for (int k0 = 0; k0 < NH; k0 += 8) {
#pragma unroll
        for (int u = 0; u < 8; u++)
            acc[u] = fmaf(bmx[k0 + u] + bmh[k0 + u], Whm[(size_t)(k0 + u) * NG + n], acc[u]);
    }
    float s = bih[n] + bhm[n];
#pragma unroll
    for (int u = 0; u < 8; u++) s += acc[u];
    g_bvp[perm_col(n)] = s;
}

// fp32 SIMT GEMM for small weight prep
template <bool HASC>
__global__ __launch_bounds__(256)
void gemm64(const float* __restrict__ A, const float* __restrict__ Bm,
            const float* __restrict__ Cadd, float* __restrict__ Out,
            int M, int N, int K) {
    __shared__ float sA[16][64];
    __shared__ float sB[16][64];
    const int bm = blockIdx.y * 64, bn = blockIdx.x * 64;
    const int tid  = threadIdx.x;
    const int arow = tid >> 2, akq = tid & 3;
    const int brow = tid >> 4, bnq = tid & 15;
    const int tr   = tid >> 4, tcx = tid & 15;
    float acc[4][4] = {};
    for (int k0 = 0; k0 < K; k0 += 16) {
        float4 av = *reinterpret_cast<const float4*>(A + (size_t)(bm + arow) * K + k0 + akq * 4);
        float4 bv = *reinterpret_cast<const float4*>(Bm + (size_t)(k0 + brow) * N + bn + bnq * 4);
        __syncthreads();
        sA[akq * 4 + 0][arow] = av.x; sA[akq * 4 + 1][arow] = av.y;
        sA[akq * 4 + 2][arow] = av.z; sA[akq * 4 + 3][arow] = av.w;
        *reinterpret_cast<float4*>(&sB[brow][bnq * 4]) = bv;
        __syncthreads();
#pragma unroll
        for (int k = 0; k < 16; k++) {
            float4 a = *reinterpret_cast<float4*>(&sA[k][tr * 4]);
            float4 b = *reinterpret_cast<float4*>(&sB[k][tcx * 4]);
            float aa[4] = {a.x, a.y, a.z, a.w};
            float bb[4] = {b.x, b.y, b.z, b.w};
#pragma unroll
            for (int i = 0; i < 4; i++)
#pragma unroll
                for (int j = 0; j < 4; j++)
                    acc[i][j] = fmaf(aa[i], bb[j], acc[i][j]);
        }
    }
#pragma unroll
    for (int i = 0; i < 4; i++) {
        int m = bm + tr * 4 + i, n = bn + tcx * 4;
        float4 r = make_float4(acc[i][0], acc[i][1], acc[i][2], acc[i][3]);
        if (HASC) {
            float4 c = *reinterpret_cast<const float4*>(Cadd + (size_t)m * N + n);
            r.x += c.x; r.y += c.y; r.z += c.z; r.w += c.w;
        }
        *reinterpret_cast<float4*>(Out + (size_t)m * N + n) = r;
    }
}

// transpose + permute + hi/lo split -> weight concat [2048 perm][3K] = [hi|lo|hi]
__global__ void tsplit_kernel(const float* __restrict__ src, int K,
                              __nv_bfloat16* __restrict__ out) {
    __shared__ float sA[32][33];
    const int n0 = blockIdx.x * 32, k0 = blockIdx.y * 32;
    const int t = threadIdx.x;
    {
        int nl = t & 31, rr = t >> 5;
#pragma unroll
        for (int it = 0; it < 4; it++) {
            int kl = it * 8 + rr;
            sA[kl][nl] = src[(size_t)(k0 + kl) * NG + n0 + nl];
        }
    }
    __syncthreads();
    int nlo = t >> 3, ks = t & 7;
    int np = perm_col(n0 + nlo);
    union { __nv_bfloat16 b[4]; uint2 u; } H, L;
#pragma unroll
    for (int kk = 0; kk < 4; kk++) {
        float v = sA[ks * 4 + kk][nlo];
        H.b[kk] = __float2bfloat16_rn(v);
        L.b[kk] = __float2bfloat16_rn(v - __bfloat162float(H.b[kk]));
    }
    size_t base = (size_t)np * (3 * K) + k0 + ks * 4;
    *reinterpret_cast<uint2*>(out + base)         = H.u;
    *reinterpret_cast<uint2*>(out + base + K)     = L.u;
    *reinterpret_cast<uint2*>(out + base + 2 * K) = H.u;
}

// x fp32 [m][256] -> xcat bf16 [m][768] = [hi|hi|lo]
__global__ void xsplit_kernel(const float* __restrict__ x) {
    size_t i = (size_t)blockIdx.x * blockDim.x + threadIdx.x;  // float4 index
    float4 v = reinterpret_cast<const float4*>(x)[i];
    float f[4] = {v.x, v.y, v.z, v.w};
    union { __nv_bfloat16 b[4]; uint2 u; } H, L;
#pragma unroll
    for (int k = 0; k < 4; k++) {
        H.b[k] = __float2bfloat16_rn(f[k]);
        L.b[k] = __float2bfloat16_rn(f[k] - __bfloat162float(H.b[k]));
    }
    size_t m = i >> 6, c = (i & 63) * 4;
    __nv_bfloat16* row = g_xcat + m * (3 * NC) + c;
    *reinterpret_cast<uint2*>(row)            = H.u;
    *reinterpret_cast<uint2*>(row + NC)       = H.u;
    *reinterpret_cast<uint2*>(row + 2 * NC)   = L.u;
}

// ===================== P GEMM (HMMA, writes time-major P) ===================
__global__ __launch_bounds__(256)
void pgemm_mma(const __nv_bfloat16* __restrict__ A,
               const __nv_bfloat16* __restrict__ Bw, int Kc) {
    constexpr int BM = 128, BN = 128, WN_ = 4, MF = 4;
    __shared__ __nv_bfloat16 sA[2][BM][40];
    __shared__ __nv_bfloat16 sB[2][BN][40];
    const int tid = threadIdx.x, lane = tid & 31, w = tid >> 5;
    const int wn0 = (w % WN_) * 32, wm0 = (w / WN_) * 64;
    const int m0 = blockIdx.y * BM, n0 = blockIdx.x * BN;

    auto load_stage = [&](int s, int k0) {
#pragma unroll
        for (int i = 0; i < (BM + BN) * 4 / 256; i++) {
            int q = i * 256 + tid;
            const __nv_bfloat16* src;
            uint32_t dst;
            if (q < BM * 4) {
                int r = q >> 2, c = q & 3;
                src = A + (size_t)(m0 + r) * Kc + k0 + c * 8;
                dst = smem_u32_of(&sA[s][r][c * 8]);
            } else {
                int q2 = q - BM * 4, r = q2 >> 2, c = q2 & 3;
                src = Bw + (size_t)(n0 + r) * Kc + k0 + c * 8;
                dst = smem_u32_of(&sB[s][r][c * 8]);
            }
            asm volatile("cp.async.cg.shared.global [%0], [%1], 16;" :: "r"(dst), "l"(src));
        }
        asm volatile("cp.async.commit_group;");
    };

    float acc[MF][4][4] = {};
    const int arow = (lane & 7) + ((lane >> 3) & 1) * 8;
    const int akm  = (lane >> 4) & 1;
    const int brow = lane & 7;
    const int bkm  = (lane >> 3) & 1;

    const int NIT = Kc >> 5;
    load_stage(0, 0);
    for (int it = 0; it < NIT; it++) {
        if (it + 1 < NIT) {
            load_stage((it + 1) & 1, (it + 1) * 32);
            asm volatile("cp.async.wait_group 1;");
        } else {
            asm volatile("cp.async.wait_group 0;");
        }
        __syncthreads();
        int s = it & 1;
#pragma unroll
        for (int ks = 0; ks < 2; ks++) {
            uint32_t aR[MF][4], bR[4][2];
#pragma unroll
            for (int ni = 0; ni < 4; ni++) {
                uint32_t ad = smem_u32_of(&sB[s][wn0 + ni * 8 + brow][ks * 16 + bkm * 8]);
                asm volatile("ldmatrix.sync.aligned.m8n8.x2.shared.b16 {%0,%1}, [%2];"
                             : "=r"(bR[ni][0]), "=r"(bR[ni][1]) : "r"(ad));
            }
#pragma unroll
            for (int mi = 0; mi < MF; mi++) {
                uint32_t ad = smem_u32_of(&sA[s][wm0 + mi * 16 + arow][ks * 16 + akm * 8]);
                asm volatile("ldmatrix.sync.aligned.m8n8.x4.shared.b16 {%0,%1,%2,%3}, [%4];"
                             : "=r"(aR[mi][0]), "=r"(aR[mi][1]), "=r"(aR[mi][2]), "=r"(aR[mi][3])
                             : "r"(ad));
            }
#pragma unroll
            for (int mi = 0; mi < MF; mi++)
#pragma unroll
                for (int ni = 0; ni < 4; ni++)
                    asm volatile(
                        "mma.sync.aligned.m16n8k16.row.col.f32.bf16.bf16.f32 "
                        "{%0,%1,%2,%3}, {%4,%5,%6,%7}, {%8,%9}, {%0,%1,%2,%3};"
                        : "+f"(acc[mi][ni][0]), "+f"(acc[mi][ni][1]),
                          "+f"(acc[mi][ni][2]), "+f"(acc[mi][ni][3])
                        : "r"(aR[mi][0]), "r"(aR[mi][1]), "r"(aR[mi][2]), "r"(aR[mi][3]),
                          "r"(bR[ni][0]), "r"(bR[ni][1]));
        }
        __syncthreads();
    }

    // P[t][b][col] = acc + bias ;  src row r = b*NL + t
#pragma unroll
    for (int mi = 0; mi < MF; mi++) {
#pragma unroll
        for (int half = 0; half < 2; half++) {
            int r = m0 + wm0 + mi * 16 + (lane >> 2) + half * 8;
            size_t dr = (size_t)(r & (NL - 1)) * NB + (size_t)(r >> 7);
#pragma unroll
            for (int ni = 0; ni < 4; ni++) {
                int col = n0 + wn0 + ni * 8 + (lane & 3) * 2;
                *reinterpret_cast<float2*>(&g_P[dr * NG + col]) =
                    make_float2(acc[mi][ni][half * 2 + 0] + g_bvp[col],
                                acc[mi][ni][half * 2 + 1] + g_bvp[col + 1]);
            }
        }
    }
}

// ===================== persistent scan kernel ===============================
// Grid (32 n-tiles, 4 m-groups) = 128 blocks, 256 threads. B tile resident in
// SMEM for all 128 steps; h streamed from L2; per-m-group counter barrier.
static constexpr int SB_PITCH = 1544;                 // bf16 elems (3088B, 16B-mult)
static constexpr int SA_PITCH = 72;                   // bf16 elems (144B)
static constexpr int SCAN_SMEM = (64 * SB_PITCH + 3 * 64 * SA_PITCH) * 2;  // 225,280B

__global__ __launch_bounds__(256)
void scan_kernel(float* __restrict__ out) {
    extern __shared__ __nv_bfloat16 sm[];
    __nv_bfloat16* sB = sm;                           // [64][1544]
    __nv_bfloat16* sA = sm + 64 * SB_PITCH;           // [3][64][72]
    const int tid = threadIdx.x, lane = tid & 31, w = tid >> 5;
    const int n0 = blockIdx.x * 64, m0 = blockIdx.y * 64, grp = blockIdx.y;
    const int wn0 = (w & 1) * 32, wm0 = (w >> 1) * 16;

    // ---- load resident B tile: W'cat rows n0..n0+63, 1536 cols -------------
    for (int i = 0; i < 48; i++) {
        int q = i * 256 + tid;                        // 12288 16B-chunks
        int r = q / 192, c = q % 192;
        asm volatile("cp.async.cg.shared.global [%0], [%1], 16;"
                     :: "r"(smem_u32_of(sB + r * SB_PITCH + c * 8)),
                        "l"(g_Wpcat + (size_t)(n0 + r) * 1536 + c * 8));
    }
    asm volatile("cp.async.commit_group;");
    asm volatile("cp.async.wait_group 0;");
    __syncthreads();

    const int arow = (lane & 7) + ((lane >> 3) & 1) * 8;
    const int akm  = (lane >> 4) & 1;
    const int browB = ((lane >> 4) & 1) * 8 + (lane & 7);   // x4 B pattern
    const int bkmB  = (lane >> 3) & 1;
    const int p0 = (lane & 3) * 2;
    const int uhi = (n0 + wn0) >> 5;
    const int j = uhi * 8 + p0;                       // hidden unit (even)

    for (int t = 0; t < NL; t++) {
        const int par = t & 1;
        const __nv_bfloat16* hsrc = g_hcat[par];

        // prefetch P for this thread's epilogue (independent of h)
        float2 pv[2][4];
        {
            const float* Pt = g_P + (size_t)t * NB * NG;
#pragma unroll
            for (int half = 0; half < 2; half++) {
                int b = m0 + wm0 + (lane >> 2) + half * 8;
#pragma unroll
                for (int ni = 0; ni < 4; ni++)
                    pv[half][ni] = __ldg(reinterpret_cast<const float2*>(
                        Pt + (size_t)b * NG + n0 + wn0 + ni * 8 + p0));
            }
        }

        // prefetch A chunks 0,1 (64 k-cols each: 512 16B-chunks -> 2/thread)
        auto prefA = [&](int c) {
            int st = c % 3, k0 = c * 64;
#pragma unroll
            for (int i = 0; i < 2; i++) {
                int q = i * 256 + tid, r = q >> 3, cc = q & 7;
                asm volatile("cp.async.cg.shared.global [%0], [%1], 16;"
                             :: "r"(smem_u32_of(sA + st * 64 * SA_PITCH + r * SA_PITCH + cc * 8)),
                                "l"(hsrc + (size_t)(m0 + r) * 1536 + k0 + cc * 8));
            }
            asm volatile("cp.async.commit_group;");
        };
        prefA(0);
        prefA(1);

        float acc[4][4] = {};
        for (int c = 0; c < 24; c++) {
            asm volatile("cp.async.wait_group 1;");
            __syncthreads();
            const __nv_bfloat16* As = sA + (c % 3) * 64 * SA_PITCH;
            const int k0 = c * 64;
#pragma unroll
            for (int ks = 0; ks < 4; ks++) {
                uint32_t aR[4];
                asm volatile("ldmatrix.sync.aligned.m8n8.x4.shared.b16 {%0,%1,%2,%3}, [%4];"
                             : "=r"(aR[0]), "=r"(aR[1]), "=r"(aR[2]), "=r"(aR[3])
                             : "r"(smem_u32_of(As + (wm0 + arow) * SA_PITCH + ks * 16 + akm * 8)));
#pragma unroll
                for (int p = 0; p < 2; p++) {
                    uint32_t b4[4];
                    asm volatile("ldmatrix.sync.aligned.m8n8.x4.shared.b16 {%0,%1,%2,%3}, [%4];"
                                 : "=r"(b4[0]), "=r"(b4[1]), "=r"(b4[2]), "=r"(b4[3])
                                 : "r"(smem_u32_of(sB + (wn0 + p * 16 + browB) * SB_PITCH
                                                   + k0 + ks * 16 + bkmB * 8)));
                    asm volatile(
                        "mma.sync.aligned.m16n8k16.row.col.f32.bf16.bf16.f32 "
                        "{%0,%1,%2,%3}, {%4,%5,%6,%7}, {%8,%9}, {%0,%1,%2,%3};"
                        : "+f"(acc[2 * p][0]), "+f"(acc[2 * p][1]),
                          "+f"(acc[2 * p][2]), "+f"(acc[2 * p][3])
                        : "r"(aR[0]), "r"(aR[1]), "r"(aR[2]), "r"(aR[3]),
                          "r"(b4[0]), "r"(b4[1]));
                    asm volatile(
                        "mma.sync.aligned.m16n8k16.row.col.f32.bf16.bf16.f32 "
                        "{%0,%1,%2,%3}, {%4,%5,%6,%7}, {%8,%9}, {%0,%1,%2,%3};"
                        : "+f"(acc[2 * p + 1][0]), "+f"(acc[2 * p + 1][1]),
                          "+f"(acc[2 * p + 1][2]), "+f"(acc[2 * p + 1][3])
                        : "r"(aR[0]), "r"(aR[1]), "r"(aR[2]), "r"(aR[3]),
                          "r"(b4[2]), "r"(b4[3]));
                }
            }
            if (c + 2 < 24) prefA(c + 2);
            else asm volatile("cp.async.commit_group;");
        }

        // ---- fused LSTM pointwise epilogue ---------------------------------
        __nv_bfloat16* hdst = g_hcat[par ^ 1];
#pragma unroll
        for (int half = 0; half < 2; half++) {
            int b = m0 + wm0 + (lane >> 2) + half * 8;
            float2 cold = *reinterpret_cast<float2*>(&g_Cst[(size_t)b * NH + j]);
            float hn[2], cn[2];
#pragma unroll
            for (int e = 0; e < 2; e++) {
                int a = half * 2 + e;
                float iv = acc[0][a] + (e ? pv[half][0].y : pv[half][0].x);
                float fv = acc[1][a] + (e ? pv[half][1].y : pv[half][1].x);
                float gv = acc[2][a] + (e ? pv[half][2].y : pv[half][2].x);
                float ov = acc[3][a] + (e ? pv[half][3].y : pv[half][3].x);
                float si = 1.f / (1.f + expf(-iv));
                float sf = 1.f / (1.f + expf(-fv));
                float so = 1.f / (1.f + expf(-ov));
                float tg = tanhf(gv);
                float Cn = sf * (e ? cold.y : cold.x) + si * tg;
                cn[e] = Cn;
                hn[e] = so * tanhf(Cn);
            }
            *reinterpret_cast<float2*>(&g_Cst[(size_t)b * NH + j]) = make_float2(cn[0], cn[1]);
            size_t o = (size_t)b * (NL * NH) + (size_t)t * NH + j;
            *reinterpret_cast<float2*>(&out[o]) = make_float2(hn[0], hn[1]);
            *reinterpret_cast<float2*>(&out[o + (size_t)NB * NL * NH]) = make_float2(cn[0], cn[1]);
            __nv_bfloat16 h0 = __float2bfloat16_rn(hn[0]);
            __nv_bfloat16 h1 = __float2bfloat16_rn(hn[1]);
            __nv_bfloat162 hh = __halves2bfloat162(h0, h1);
            __nv_bfloat162 hl = __halves2bfloat162(
                __float2bfloat16_rn(hn[0] - __bfloat162float(h0)),
                __float2bfloat16_rn(hn[1] - __bfloat162float(h1)));
            __nv_bfloat16* hb = hdst + (size_t)b * (3 * NH);
            *reinterpret_cast<__nv_bfloat162*>(hb + j)          = hh;
            *reinterpret_cast<__nv_bfloat162*>(hb + j + NH)     = hh;
            *reinterpret_cast<__nv_bfloat162*>(hb + j + 2 * NH) = hl;
        }

        // ---- per-m-group barrier ------------------------------------------
        __threadfence();
        __syncthreads();
        if (tid == 0) {
            atomicAdd(&g_bar[grp], 1);
            int target = 32 * (t + 1);
            while (*((volatile int*)&g_bar[grp]) < target) __nanosleep(64);
        }
        __syncthreads();
    }
}

// ===================== x_tilde ==============================================
__global__ void xtilde_kernel(const float* __restrict__ x, const float* __restrict__ Wa,
                              const float* __restrict__ ba, float* __restrict__ out) {
    __shared__ float red[NC];
    __shared__ float s_wa[NL];
    int b = blockIdx.x, c = threadIdx.x;
    if (c < NL) s_wa[c] = Wa[2 * NH + c];
    __syncthreads();
    const float* xb = x + (size_t)b * NL * NC;
    float s = ba[0];
#pragma unroll 4
    for (int l = 0; l < NL; l++) s = fmaf(xb[(size_t)l * NC + c], s_wa[l], s);
    red[c] = s; __syncthreads();
    for (int o = NC / 2; o > 0; o >>= 1) { if (c < o) red[c] = fmaxf(red[c], red[c + o]); __syncthreads(); }
    float mx = red[0]; __syncthreads();
    float e = expf(s - mx);
    red[c] = e; __syncthreads();
    for (int o = NC / 2; o > 0; o >>= 1) { if (c < o) red[c] += red[c + o]; __syncthreads(); }
    float alpha = e / red[0];
    float* ob = out + (size_t)b * NL * NC;
#pragma unroll 4
    for (int l = 0; l < NL; l++) ob[(size_t)l * NC + c] = alpha * xb[(size_t)l * NC + c];
}

// ===================== host =================================================
extern "C" void kernel_launch(void* const* d_in, const int* in_sizes, int n_in,
                              void* d_out, int out_size) {
    const float* x   = (const float*)d_in[0];
    const float* Wih = (const float*)d_in[1];
    const float* bih = (const float*)d_in[2];
    const float* Wmx = (const float*)d_in[3];
    const float* bmx = (const float*)d_in[4];
    const float* Wmh = (const float*)d_in[5];
    const float* bmh = (const float*)d_in[6];
    const float* Whm = (const float*)d_in[7];
    const float* bhm = (const float*)d_in[8];
    const float* Wa  = (const float*)d_in[9];
    const float* ba  = (const float*)d_in[10];
    float* out = (float*)d_out;

    float *pWp, *pWb;
    __nv_bfloat16 *pWpc, *pWbc, *pXc;
    cudaGetSymbolAddress((void**)&pWp,  g_Wp);
    cudaGetSymbolAddress((void**)&pWb,  g_Wb);
    cudaGetSymbolAddress((void**)&pWpc, g_Wpcat);
    cudaGetSymbolAddress((void**)&pWbc, g_Wbcat);
    cudaGetSymbolAddress((void**)&pXc,  g_xcat);

    cudaFuncSetAttribute(scan_kernel, cudaFuncAttributeMaxDynamicSharedMemorySize, SCAN_SMEM);

    init_state_kernel<<<(NB * 3 * NH + 255) / 256, 256>>>();

    // folded weights (fp32 SIMT — small)
    gemm64<false><<<dim3(NG / 64, NH / 64), 256>>>(Wmh, Whm, nullptr, pWp, NH, NG, NH);
    gemm64<true ><<<dim3(NG / 64, NC / 64), 256>>>(Wmx, Whm, Wih, pWb, NC, NG, NH);
    bvec_kernel<<<NG / 256, 256>>>(bih, bhm, bmx, bmh, Whm);

    // transpose+permute+split to K-concat bf16
    tsplit_kernel<<<dim3(NG / 32, NH / 32), 256>>>(pWp, NH, pWpc);
    tsplit_kernel<<<dim3(NG / 32, NC / 32), 256>>>(pWb, NC, pWbc);
    xsplit_kernel<<<(NB * NL * NC / 4) / 256, 256>>>(x);

    // P = x @ Wbig + bias  (HMMA, time-major output)
    pgemm_mma<<<dim3(NG / 128, (NB * NL) / 128), 256>>>(pXc, pWbc, 3 * NC);

    // x_tilde (softmax over c is time-invariant)
    xtilde_kernel<<<NB, 256>>>(x, Wa, ba, out + (size_t)2 * NB * NL * NH);

    // persistent fused scan: all 128 steps in ONE launch
    scan_kernel<<<dim3(32, 4), 256, SCAN_SMEM>>>(out);
}

// round 7
// speedup vs baseline: 3.2843x; 1.4796x over previous
#include <cuda_runtime.h>
#include <cuda_bf16.h>
#include <cuda_fp16.h>
#include <math.h>
#include <stdint.h>

#define NB 256   // batch
#define NL 128   // seq len
#define NC 256   // input channels
#define NH 512   // hidden
#define NG 2048  // 4*H

__device__ __forceinline__ uint32_t smem_u32_of(const void* p) {
    uint32_t a;
    asm("{ .reg .u64 t; cvta.to.shared.u64 t, %1; cvt.u32.u64 %0, t; }" : "=r"(a) : "l"(p));
    return a;
}

// ===================== device globals (no allocation allowed) ===============
__device__ float g_Wp[(size_t)NH * NG];               // W' = Wmh@Whm (fp32)
__device__ float g_Wb[(size_t)NC * NG];               // Wbig = Wih + Wmx@Whm
__device__ float g_bvp[NG];                           // folded bias, permuted cols
__device__ __half g_Wp16[(size_t)NG * NH];            // fp16(W'^T) permuted [n'][512]
__device__ __nv_bfloat16 g_Wbcat[(size_t)NG * (3 * NC)];     // [n' perm][768] = [hi|lo|hi]
__device__ __nv_bfloat16 g_xcat[(size_t)NB * NL * (3 * NC)]; // [m][768] = [hi|hi|lo]
__device__ __half g_hA[2][(size_t)NB * 1024];         // [b][1024] = [h1(512)|h2(512)]
__device__ float g_P[(size_t)NL * NB * NG];           // TIME-MAJOR: [t][b][n']
__device__ float g_Cst[(size_t)NB * NH];              // cell state
__device__ int   g_bar[4];                            // per-m-group barrier counters

// ===================== prep kernels =========================================
__global__ void init_state_kernel() {
    int i = blockIdx.x * blockDim.x + threadIdx.x;
    if (i < NB * 1024) g_hA[0][i] = __float2half_rn(0.f);
    if (i < NB * NH) g_Cst[i] = 0.f;
    if (i < NG) g_bvp[i] = 0.f;
    if (i < 4) g_bar[i] = 0;
}

__device__ __forceinline__ int perm_col(int n) {       // natural gate col -> permuted
    int j = n & 511, g = n >> 9;
    return ((j >> 3) << 5) | (g << 3) | (j & 7);
}

// split-K bvec: grid (8 n-blocks, 8 k-slices), atomicAdd into zeroed g_bvp
__global__ void bvec_kernel(const float* __restrict__ bih, const float* __restrict__ bhm,
                            const float* __restrict__ bmx, const float* __restrict__ bmh,
                            const float* __restrict__ Whm) {
    int n = blockIdx.x * blockDim.x + threadIdx.x;
    int k0 = blockIdx.y * 64;
    float acc[8] = {};
    for (int kk = 0; kk < 64; kk += 8) {
#pragma unroll
        for (int u = 0; u < 8; u++) {
            int k = k0 + kk + u;
            acc[u] = fmaf(bmx[k] + bmh[k], Whm[(size_t)k * NG + n], acc[u]);
        }
    }
    float s = (blockIdx.y == 0) ? (bih[n] + bhm[n]) : 0.f;
#pragma unroll
    for (int u = 0; u < 8; u++) s += acc[u];
    atomicAdd(&g_bvp[perm_col(n)], s);
}

// fp32 SIMT GEMM for small weight prep
template <bool HASC>
__global__ __launch_bounds__(256)
void gemm64(const float* __restrict__ A, const float* __restrict__ Bm,
            const float* __restrict__ Cadd, float* __restrict__ Out,
            int M, int N, int K) {
    __shared__ float sA[16][64];
    __shared__ float sB[16][64];
    const int bm = blockIdx.y * 64, bn = blockIdx.x * 64;
    const int tid  = threadIdx.x;
    const int arow = tid >> 2, akq = tid & 3;
    const int brow = tid >> 4, bnq = tid & 15;
    const int tr   = tid >> 4, tcx = tid & 15;
    float acc[4][4] = {};
    for (int k0 = 0; k0 < K; k0 += 16) {
        float4 av = *reinterpret_cast<const float4*>(A + (size_t)(bm + arow) * K + k0 + akq * 4);
        float4 bv = *reinterpret_cast<const float4*>(Bm + (size_t)(k0 + brow) * N + bn + bnq * 4);
        __syncthreads();
        sA[akq * 4 + 0][arow] = av.x; sA[akq * 4 + 1][arow] = av.y;
        sA[akq * 4 + 2][arow] = av.z; sA[akq * 4 + 3][arow] = av.w;
        *reinterpret_cast<float4*>(&sB[brow][bnq * 4]) = bv;
        __syncthreads();
#pragma unroll
        for (int k = 0; k < 16; k++) {
            float4 a = *reinterpret_cast<float4*>(&sA[k][tr * 4]);
            float4 b = *reinterpret_cast<float4*>(&sB[k][tcx * 4]);
            float aa[4] = {a.x, a.y, a.z, a.w};
            float bb[4] = {b.x, b.y, b.z, b.w};
#pragma unroll
            for (int i = 0; i < 4; i++)
#pragma unroll
                for (int j = 0; j < 4; j++)
                    acc[i][j] = fmaf(aa[i], bb[j], acc[i][j]);
        }
    }
#pragma unroll
    for (int i = 0; i < 4; i++) {
        int m = bm + tr * 4 + i, n = bn + tcx * 4;
        float4 r = make_float4(acc[i][0], acc[i][1], acc[i][2], acc[i][3]);
        if (HASC) {
            float4 c = *reinterpret_cast<const float4*>(Cadd + (size_t)m * N + n);
            r.x += c.x; r.y += c.y; r.z += c.z; r.w += c.w;
        }
        *reinterpret_cast<float4*>(Out + (size_t)m * N + n) = r;
    }
}

// transpose + permute + hi/lo split -> bf16 concat [2048 perm][3K] = [hi|lo|hi]
__global__ void tsplit_kernel(const float* __restrict__ src, int K,
                              __nv_bfloat16* __restrict__ out) {
    __shared__ float sA[32][33];
    const int n0 = blockIdx.x * 32, k0 = blockIdx.y * 32;
    const int t = threadIdx.x;
    {
        int nl = t & 31, rr = t >> 5;
#pragma unroll
        for (int it = 0; it < 4; it++) {
            int kl = it * 8 + rr;
            sA[kl][nl] = src[(size_t)(k0 + kl) * NG + n0 + nl];
        }
    }
    __syncthreads();
    int nlo = t >> 3, ks = t & 7;
    int np = perm_col(n0 + nlo);
    union { __nv_bfloat16 b[4]; uint2 u; } H, L;
#pragma unroll
    for (int kk = 0; kk < 4; kk++) {
        float v = sA[ks * 4 + kk][nlo];
        H.b[kk] = __float2bfloat16_rn(v);
        L.b[kk] = __float2bfloat16_rn(v - __bfloat162float(H.b[kk]));
    }
    size_t base = (size_t)np * (3 * K) + k0 + ks * 4;
    *reinterpret_cast<uint2*>(out + base)         = H.u;
    *reinterpret_cast<uint2*>(out + base + K)     = L.u;
    *reinterpret_cast<uint2*>(out + base + 2 * K) = H.u;
}

// transpose + permute -> fp16 W' [2048 perm][512]
__global__ void wsplit16_kernel(const float* __restrict__ src) {
    __shared__ float sA[32][33];
    const int n0 = blockIdx.x * 32, k0 = blockIdx.y * 32;
    const int t = threadIdx.x;
    {
        int nl = t & 31, rr = t >> 5;
#pragma unroll
        for (int it = 0; it < 4; it++) {
            int kl = it * 8 + rr;
            sA[kl][nl] = src[(size_t)(k0 + kl) * NG + n0 + nl];
        }
    }
    __syncthreads();
    int nlo = t >> 3, ks = t & 7;
    int np = perm_col(n0 + nlo);
    union { __half h[4]; uint2 u; } H;
#pragma unroll
    for (int kk = 0; kk < 4; kk++)
        H.h[kk] = __float2half_rn(sA[ks * 4 + kk][nlo]);
    *reinterpret_cast<uint2*>(g_Wp16 + (size_t)np * NH + k0 + ks * 4) = H.u;
}

// x fp32 [m][256] -> xcat bf16 [m][768] = [hi|hi|lo]
__global__ void xsplit_kernel(const float* __restrict__ x) {
    size_t i = (size_t)blockIdx.x * blockDim.x + threadIdx.x;  // float4 index
    float4 v = reinterpret_cast<const float4*>(x)[i];
    float f[4] = {v.x, v.y, v.z, v.w};
    union { __nv_bfloat16 b[4]; uint2 u; } H, L;
#pragma unroll
    for (int k = 0; k < 4; k++) {
        H.b[k] = __float2bfloat16_rn(f[k]);
        L.b[k] = __float2bfloat16_rn(f[k] - __bfloat162float(H.b[k]));
    }
    size_t m = i >> 6, c = (i & 63) * 4;
    __nv_bfloat16* row = g_xcat + m * (3 * NC) + c;
    *reinterpret_cast<uint2*>(row)            = H.u;
    *reinterpret_cast<uint2*>(row + NC)       = H.u;
    *reinterpret_cast<uint2*>(row + 2 * NC)   = L.u;
}

// ===================== P GEMM (HMMA bf16, time-major P out) =================
__global__ __launch_bounds__(256)
void pgemm_mma(const __nv_bfloat16* __restrict__ A,
               const __nv_bfloat16* __restrict__ Bw, int Kc) {
    constexpr int BM = 128, BN = 128, WN_ = 4, MF = 4;
    __shared__ __nv_bfloat16 sA[2][BM][40];
    __shared__ __nv_bfloat16 sB[2][BN][40];
    const int tid = threadIdx.x, lane = tid & 31, w = tid >> 5;
    const int wn0 = (w % WN_) * 32, wm0 = (w / WN_) * 64;
    const int m0 = blockIdx.y * BM, n0 = blockIdx.x * BN;

    auto load_stage = [&](int s, int k0) {
#pragma unroll
        for (int i = 0; i < (BM + BN) * 4 / 256; i++) {
            int q = i * 256 + tid;
            const __nv_bfloat16* src;
            uint32_t dst;
            if (q < BM * 4) {
                int r = q >> 2, c = q & 3;
                src = A + (size_t)(m0 + r) * Kc + k0 + c * 8;
                dst = smem_u32_of(&sA[s][r][c * 8]);
            } else {
                int q2 = q - BM * 4, r = q2 >> 2, c = q2 & 3;
                src = Bw + (size_t)(n0 + r) * Kc + k0 + c * 8;
                dst = smem_u32_of(&sB[s][r][c * 8]);
            }
            asm volatile("cp.async.cg.shared.global [%0], [%1], 16;" :: "r"(dst), "l"(src));
        }
        asm volatile("cp.async.commit_group;");
    };

    float acc[MF][4][4] = {};
    const int arow = (lane & 7) + ((lane >> 3) & 1) * 8;
    const int akm  = (lane >> 4) & 1;
    const int brow = lane & 7;
    const int bkm  = (lane >> 3) & 1;

    const int NIT = Kc >> 5;
    load_stage(0, 0);
    for (int it = 0; it < NIT; it++) {
        if (it + 1 < NIT) {
            load_stage((it + 1) & 1, (it + 1) * 32);
            asm volatile("cp.async.wait_group 1;");
        } else {
            asm volatile("cp.async.wait_group 0;");
        }
        __syncthreads();
        int s = it & 1;
#pragma unroll
        for (int ks = 0; ks < 2; ks++) {
            uint32_t aR[MF][4], bR[4][2];
#pragma unroll
            for (int ni = 0; ni < 4; ni++) {
                uint32_t ad = smem_u32_of(&sB[s][wn0 + ni * 8 + brow][ks * 16 + bkm * 8]);
                asm volatile("ldmatrix.sync.aligned.m8n8.x2.shared.b16 {%0,%1}, [%2];"
                             : "=r"(bR[ni][0]), "=r"(bR[ni][1]) : "r"(ad));
            }
#pragma unroll
            for (int mi = 0; mi < MF; mi++) {
                uint32_t ad = smem_u32_of(&sA[s][wm0 + mi * 16 + arow][ks * 16 + akm * 8]);
                asm volatile("ldmatrix.sync.aligned.m8n8.x4.shared.b16 {%0,%1,%2,%3}, [%4];"
                             : "=r"(aR[mi][0]), "=r"(aR[mi][1]), "=r"(aR[mi][2]), "=r"(aR[mi][3])
                             : "r"(ad));
            }
#pragma unroll
            for (int mi = 0; mi < MF; mi++)
#pragma unroll
                for (int ni = 0; ni < 4; ni++)
                    asm volatile(
                        "mma.sync.aligned.m16n8k16.row.col.f32.bf16.bf16.f32 "
                        "{%0,%1,%2,%3}, {%4,%5,%6,%7}, {%8,%9}, {%0,%1,%2,%3};"
                        : "+f"(acc[mi][ni][0]), "+f"(acc[mi][ni][1]),
                          "+f"(acc[mi][ni][2]), "+f"(acc[mi][ni][3])
                        : "r"(aR[mi][0]), "r"(aR[mi][1]), "r"(aR[mi][2]), "r"(aR[mi][3]),
                          "r"(bR[ni][0]), "r"(bR[ni][1]));
        }
        __syncthreads();
    }
#pragma unroll
    for (int mi = 0; mi < MF; mi++) {
#pragma unroll
        for (int half = 0; half < 2; half++) {
            int r = m0 + wm0 + mi * 16 + (lane >> 2) + half * 8;
            size_t dr = (size_t)(r & (NL - 1)) * NB + (size_t)(r >> 7);
#pragma unroll
            for (int ni = 0; ni < 4; ni++) {
                int col = n0 + wn0 + ni * 8 + (lane & 3) * 2;
                *reinterpret_cast<float2*>(&g_P[dr * NG + col]) =
                    make_float2(acc[mi][ni][half * 2 + 0] + g_bvp[col],
                                acc[mi][ni][half * 2 + 1] + g_bvp[col + 1]);
            }
        }
    }
}

// ===================== persistent scan kernel ===============================
// fp16 2-term: gates_rec = (h1+h2) @ W1, W1 = fp16(W') resident in SMEM.
// A per step: [64 b][1024] fp16; 8 chunks of 128 k, ALL issued up front.
static constexpr int SBP = 520;                        // halves (1040 B pitch)
static constexpr int SAP = 136;                        // halves (272 B pitch)
static constexpr int SA_STAGE = 64 * SAP;
static constexpr int SCAN_SMEM = (64 * SBP + 8 * SA_STAGE) * 2;   // 205,824 B

__device__ __forceinline__ void wait_grp(int n) {
    switch (n) {
        case 0: asm volatile("cp.async.wait_group 0;" ::: "memory"); break;
        case 1: asm volatile("cp.async.wait_group 1;" ::: "memory"); break;
        case 2: asm volatile("cp.async.wait_group 2;" ::: "memory"); break;
        case 3: asm volatile("cp.async.wait_group 3;" ::: "memory"); break;
        case 4: asm volatile("cp.async.wait_group 4;" ::: "memory"); break;
        case 5: asm volatile("cp.async.wait_group 5;" ::: "memory"); break;
        case 6: asm volatile("cp.async.wait_group 6;" ::: "memory"); break;
        default: asm volatile("cp.async.wait_group 7;" ::: "memory"); break;
    }
}

__global__ __launch_bounds__(256)
void scan_kernel(float* __restrict__ out) {
    extern __shared__ __half sm16[];
    __half* sB = sm16;                                // [64][520]
    __half* sA = sm16 + 64 * SBP;                     // [8][64][136]
    const int tid = threadIdx.x, lane = tid & 31, w = tid >> 5;
    const int n0 = blockIdx.x * 64, m0 = blockIdx.y * 64, grp = blockIdx.y;
    const int wn0 = (w & 1) * 32, wm0 = (w >> 1) * 16;

    // ---- resident B tile: W1 rows n0..n0+63, 512 cols ----------------------
#pragma unroll
    for (int i = 0; i < 16; i++) {
        int q = i * 256 + tid;                        // 4096 16B-chunks
        int r = q >> 6, cc = q & 63;
        asm volatile("cp.async.cg.shared.global [%0], [%1], 16;"
                     :: "r"(smem_u32_of(sB + r * SBP + cc * 8)),
                        "l"(g_Wp16 + (size_t)(n0 + r) * NH + cc * 8));
    }
    asm volatile("cp.async.commit_group;");
    asm volatile("cp.async.wait_group 0;");
    __syncthreads();

    const int arow = (lane & 7) + ((lane >> 3) & 1) * 8;
    const int akm  = (lane >> 4) & 1;
    const int browB = ((lane >> 4) & 1) * 8 + (lane & 7);
    const int bkmB  = (lane >> 3) & 1;
    const int p0 = (lane & 3) * 2;
    const int j = ((n0 + wn0) >> 5) * 8 + p0;         // hidden unit (even)

    for (int t = 0; t < NL; t++) {
        const int par = t & 1;
        const __half* hsrc = g_hA[par];

        // issue ALL 8 A chunks (16 KB each) immediately
#pragma unroll
        for (int c = 0; c < 8; c++) {
#pragma unroll
            for (int i = 0; i < 4; i++) {
                int q = i * 256 + tid;
                int r = q >> 4, cc = q & 15;
                asm volatile("cp.async.cg.shared.global [%0], [%1], 16;"
                             :: "r"(smem_u32_of(sA + c * SA_STAGE + r * SAP + cc * 8)),
                                "l"(hsrc + (size_t)(m0 + r) * 1024 + c * 128 + cc * 8));
            }
            asm volatile("cp.async.commit_group;");
        }

        // P prefetch (DRAM; overlaps with chunk0 latency)
        float2 pv[2][4];
        {
            const float* Pt = g_P + (size_t)t * NB * NG;
#pragma unroll
            for (int half = 0; half < 2; half++) {
                int b = m0 + wm0 + (lane >> 2) + half * 8;
#pragma unroll
                for (int ni = 0; ni < 4; ni++)
                    pv[half][ni] = __ldg(reinterpret_cast<const float2*>(
                        Pt + (size_t)b * NG + n0 + wn0 + ni * 8 + p0));
            }
        }

        float acc[4][4] = {};
#pragma unroll
        for (int c = 0; c < 8; c++) {
            wait_grp(7 - c);
            __syncthreads();
            const __half* As = sA + c * SA_STAGE;
            const int kb = (c & 3) * 128;             // B col (W1 reused for h1,h2)
#pragma unroll
            for (int ks = 0; ks < 8; ks++) {
                uint32_t aR[4];
                asm volatile("ldmatrix.sync.aligned.m8n8.x4.shared.b16 {%0,%1,%2,%3}, [%4];"
                             : "=r"(aR[0]), "=r"(aR[1]), "=r"(aR[2]), "=r"(aR[3])
                             : "r"(smem_u32_of(As + (wm0 + arow) * SAP + ks * 16 + akm * 8)));
#pragma unroll
                for (int p = 0; p < 2; p++) {
                    uint32_t b4[4];
                    asm volatile("ldmatrix.sync.aligned.m8n8.x4.shared.b16 {%0,%1,%2,%3}, [%4];"
                                 : "=r"(b4[0]), "=r"(b4[1]), "=r"(b4[2]), "=r"(b4[3])
                                 : "r"(smem_u32_of(sB + (wn0 + p * 16 + browB) * SBP
                                                   + kb + ks * 16 + bkmB * 8)));
                    asm volatile(
                        "mma.sync.aligned.m16n8k16.row.col.f32.f16.f16.f32 "
                        "{%0,%1,%2,%3}, {%4,%5,%6,%7}, {%8,%9}, {%0,%1,%2,%3};"
                        : "+f"(acc[2 * p][0]), "+f"(acc[2 * p][1]),
                          "+f"(acc[2 * p][2]), "+f"(acc[2 * p][3])
                        : "r"(aR[0]), "r"(aR[1]), "r"(aR[2]), "r"(aR[3]),
                          "r"(b4[0]), "r"(b4[1]));
                    asm volatile(
                        "mma.sync.aligned.m16n8k16.row.col.f32.f16.f16.f32 "
                        "{%0,%1,%2,%3}, {%4,%5,%6,%7}, {%8,%9}, {%0,%1,%2,%3};"
                        : "+f"(acc[2 * p + 1][0]), "+f"(acc[2 * p + 1][1]),
                          "+f"(acc[2 * p + 1][2]), "+f"(acc[2 * p + 1][3])
                        : "r"(aR[0]), "r"(aR[1]), "r"(aR[2]), "r"(aR[3]),
                          "r"(b4[2]), "r"(b4[3]));
                }
            }
        }

        // ---- fused LSTM pointwise epilogue ---------------------------------
        __half* hdst = g_hA[par ^ 1];
#pragma unroll
        for (int half = 0; half < 2; half++) {
            int b = m0 + wm0 + (lane >> 2) + half * 8;
            float2 cold = *reinterpret_cast<float2*>(&g_Cst[(size_t)b * NH + j]);
            float hn[2], cn[2];
#pragma unroll
            for (int e = 0; e < 2; e++) {
                int a = half * 2 + e;
                float iv = acc[0][a] + (e ? pv[half][0].y : pv[half][0].x);
                float fv = acc[1][a] + (e ? pv[half][1].y : pv[half][1].x);
                float gv = acc[2][a] + (e ? pv[half][2].y : pv[half][2].x);
                float ov = acc[3][a] + (e ? pv[half][3].y : pv[half][3].x);
                float si = 1.f / (1.f + expf(-iv));
                float sf = 1.f / (1.f + expf(-fv));
                float so = 1.f / (1.f + expf(-ov));
                float tg = tanhf(gv);
                float Cn = sf * (e ? cold.y : cold.x) + si * tg;
                cn[e] = Cn;
                hn[e] = so * tanhf(Cn);
            }
            *reinterpret_cast<float2*>(&g_Cst[(size_t)b * NH + j]) = make_float2(cn[0], cn[1]);
            size_t o = (size_t)b * (NL * NH) + (size_t)t * NH + j;
            *reinterpret_cast<float2*>(&out[o]) = make_float2(hn[0], hn[1]);
            *reinterpret_cast<float2*>(&out[o + (size_t)NB * NL * NH]) = make_float2(cn[0], cn[1]);
            __half h10 = __float2half_rn(hn[0]);
            __half h11 = __float2half_rn(hn[1]);
            __half h20 = __float2half_rn(hn[0] - __half2float(h10));
            __half h21 = __float2half_rn(hn[1] - __half2float(h11));
            __half* hb = hdst + (size_t)b * 1024;
            *reinterpret_cast<__half2*>(hb + j)       = __halves2half2(h10, h11);
            *reinterpret_cast<__half2*>(hb + 512 + j) = __halves2half2(h20, h21);
        }

        // ---- per-m-group barrier ------------------------------------------
        __threadfence();
        __syncthreads();
        if (tid == 0) {
            atomicAdd(&g_bar[grp], 1);
            int target = 32 * (t + 1);
            while (*((volatile int*)&g_bar[grp]) < target) __nanosleep(64);
        }
        __syncthreads();
    }
}

// ===================== x_tilde ==============================================
__global__ void xtilde_kernel(const float* __restrict__ x, const float* __restrict__ Wa,
                              const float* __restrict__ ba, float* __restrict__ out) {
    __shared__ float red[NC];
    __shared__ float s_wa[NL];
    int b = blockIdx.x, c = threadIdx.x;
    if (c < NL) s_wa[c] = Wa[2 * NH + c];
    __syncthreads();
    const float* xb = x + (size_t)b * NL * NC;
    float s = ba[0];
#pragma unroll 4
    for (int l = 0; l < NL; l++) s = fmaf(xb[(size_t)l * NC + c], s_wa[l], s);
    red[c] = s; __syncthreads();
    for (int o = NC / 2; o > 0; o >>= 1) { if (c < o) red[c] = fmaxf(red[c], red[c + o]); __syncthreads(); }
    float mx = red[0]; __syncthreads();
    float e = expf(s - mx);
    red[c] = e; __syncthreads();
    for (int o = NC / 2; o > 0; o >>= 1) { if (c < o) red[c] += red[c + o]; __syncthreads(); }
    float alpha = e / red[0];
    float* ob = out + (size_t)b * NL * NC;
#pragma unroll 4
    for (int l = 0; l < NL; l++) ob[(size_t)l * NC + c] = alpha * xb[(size_t)l * NC + c];
}

// ===================== host =================================================
extern "C" void kernel_launch(void* const* d_in, const int* in_sizes, int n_in,
                              void* d_out, int out_size) {
    const float* x   = (const float*)d_in[0];
    const float* Wih = (const float*)d_in[1];
    const float* bih = (const float*)d_in[2];
    const float* Wmx = (const float*)d_in[3];
    const float* bmx = (const float*)d_in[4];
    const float* Wmh = (const float*)d_in[5];
    const float* bmh = (const float*)d_in[6];
    const float* Whm = (const float*)d_in[7];
    const float* bhm = (const float*)d_in[8];
    const float* Wa  = (const float*)d_in[9];
    const float* ba  = (const float*)d_in[10];
    float* out = (float*)d_out;

    float *pWp, *pWb;
    __nv_bfloat16 *pWbc, *pXc;
    cudaGetSymbolAddress((void**)&pWp,  g_Wp);
    cudaGetSymbolAddress((void**)&pWb,  g_Wb);
    cudaGetSymbolAddress((void**)&pWbc, g_Wbcat);
    cudaGetSymbolAddress((void**)&pXc,  g_xcat);

    cudaFuncSetAttribute(scan_kernel, cudaFuncAttributeMaxDynamicSharedMemorySize, SCAN_SMEM);

    init_state_kernel<<<(NB * 1024 + 255) / 256, 256>>>();

    // folded weights (fp32 SIMT — small)
    gemm64<false><<<dim3(NG / 64, NH / 64), 256>>>(Wmh, Whm, nullptr, pWp, NH, NG, NH);
    gemm64<true ><<<dim3(NG / 64, NC / 64), 256>>>(Wmx, Whm, Wih, pWb, NC, NG, NH);
    bvec_kernel<<<dim3(8, 8), 256>>>(bih, bhm, bmx, bmh, Whm);

    // weight conversions
    wsplit16_kernel<<<dim3(NG / 32, NH / 32), 256>>>(pWp);
    tsplit_kernel<<<dim3(NG / 32, NC / 32), 256>>>(pWb, NC, pWbc);
    xsplit_kernel<<<(NB * NL * NC / 4) / 256, 256>>>(x);

    // P = x @ Wbig + bias  (HMMA bf16 3-term, time-major output)
    pgemm_mma<<<dim3(NG / 128, (NB * NL) / 128), 256>>>(pXc, pWbc, 3 * NC);

    // x_tilde (softmax over c is time-invariant)
    xtilde_kernel<<<NB, 256>>>(x, Wa, ba, out + (size_t)2 * NB * NL * NH);

    // persistent fused scan: all 128 steps in ONE launch (fp16 2-term)
    scan_kernel<<<dim3(32, 4), 256, SCAN_SMEM>>>(out);
}

// round 8
// speedup vs baseline: 4.3803x; 1.3337x over previous
#include <cuda_runtime.h>
#include <cuda_bf16.h>
#include <cuda_fp16.h>
#include <math.h>
#include <stdint.h>

#define NB 256   // batch
#define NL 128   // seq len
#define NC 256   // input channels
#define NH 512   // hidden
#define NG 2048  // 4*H

__device__ __forceinline__ uint32_t smem_u32_of(const void* p) {
    uint32_t a;
    asm("{ .reg .u64 t; cvta.to.shared.u64 t, %1; cvt.u32.u64 %0, t; }" : "=r"(a) : "l"(p));
    return a;
}

// ===================== device globals (no allocation allowed) ===============
__device__ float g_Wp[(size_t)NH * NG];               // W' = Wmh@Whm (fp32)
__device__ float g_Wb[(size_t)NC * NG];               // Wbig = Wih + Wmx@Whm
__device__ float g_bvp[NG];                           // folded bias, permuted cols
__device__ __half g_Wp16[(size_t)NG * NH];            // fp16(W'^T) permuted [n'][512]
__device__ __half g_Wb16[(size_t)NG * 512];           // fp16(Wbig^T) perm [n'][512]=[W1|W1]
__device__ __half g_x16[(size_t)NB * NL * 512];       // [m][512] = [x1|x2] (hi/lo fp16)
__device__ __half g_h16[2][(size_t)NB * NH];          // hidden fp16, ping-pong
__device__ float g_P[(size_t)NL * NB * NG];           // TIME-MAJOR: [t][b][n']
__device__ float g_Cst[(size_t)NB * NH];              // cell state
__device__ int   g_bar[4];                            // per-m-group barrier counters

// ===================== prep kernels =========================================
__global__ void init_state_kernel() {
    int i = blockIdx.x * blockDim.x + threadIdx.x;
    if (i < NB * NH) { g_h16[0][i] = __float2half_rn(0.f); g_Cst[i] = 0.f; }
    if (i < NG) g_bvp[i] = 0.f;
    if (i < 4) g_bar[i] = 0;
}

__device__ __forceinline__ int perm_col(int n) {       // natural gate col -> permuted
    int j = n & 511, g = n >> 9;
    return ((j >> 3) << 5) | (g << 3) | (j & 7);
}

// split-K bvec: grid (8 n-blocks, 8 k-slices), atomicAdd into zeroed g_bvp
__global__ void bvec_kernel(const float* __restrict__ bih, const float* __restrict__ bhm,
                            const float* __restrict__ bmx, const float* __restrict__ bmh,
                            const float* __restrict__ Whm) {
    int n = blockIdx.x * blockDim.x + threadIdx.x;
    int k0 = blockIdx.y * 64;
    float acc[8] = {};
    for (int kk = 0; kk < 64; kk += 8) {
#pragma unroll
        for (int u = 0; u < 8; u++) {
            int k = k0 + kk + u;
            acc[u] = fmaf(bmx[k] + bmh[k], Whm[(size_t)k * NG + n], acc[u]);
        }
    }
    float s = (blockIdx.y == 0) ? (bih[n] + bhm[n]) : 0.f;
#pragma unroll
    for (int u = 0; u < 8; u++) s += acc[u];
    atomicAdd(&g_bvp[perm_col(n)], s);
}

// fp32 SIMT GEMM for small weight prep
template <bool HASC>
__global__ __launch_bounds__(256)
void gemm64(const float* __restrict__ A, const float* __restrict__ Bm,
            const float* __restrict__ Cadd, float* __restrict__ Out,
            int M, int N, int K) {
    __shared__ float sA[16][64];
    __shared__ float sB[16][64];
    const int bm = blockIdx.y * 64, bn = blockIdx.x * 64;
    const int tid  = threadIdx.x;
    const int arow = tid >> 2, akq = tid & 3;
    const int brow = tid >> 4, bnq = tid & 15;
    const int tr   = tid >> 4, tcx = tid & 15;
    float acc[4][4] = {};
    for (int k0 = 0; k0 < K; k0 += 16) {
        float4 av = *reinterpret_cast<const float4*>(A + (size_t)(bm + arow) * K + k0 + akq * 4);
        float4 bv = *reinterpret_cast<const float4*>(Bm + (size_t)(k0 + brow) * N + bn + bnq * 4);
        __syncthreads();
        sA[akq * 4 + 0][arow] = av.x; sA[akq * 4 + 1][arow] = av.y;
        sA[akq * 4 + 2][arow] = av.z; sA[akq * 4 + 3][arow] = av.w;
        *reinterpret_cast<float4*>(&sB[brow][bnq * 4]) = bv;
        __syncthreads();
#pragma unroll
        for (int k = 0; k < 16; k++) {
            float4 a = *reinterpret_cast<float4*>(&sA[k][tr * 4]);
            float4 b = *reinterpret_cast<float4*>(&sB[k][tcx * 4]);
            float aa[4] = {a.x, a.y, a.z, a.w};
            float bb[4] = {b.x, b.y, b.z, b.w};
#pragma unroll
            for (int i = 0; i < 4; i++)
#pragma unroll
                for (int j = 0; j < 4; j++)
                    acc[i][j] = fmaf(aa[i], bb[j], acc[i][j]);
        }
    }
#pragma unroll
    for (int i = 0; i < 4; i++) {
        int m = bm + tr * 4 + i, n = bn + tcx * 4;
        float4 r = make_float4(acc[i][0], acc[i][1], acc[i][2], acc[i][3]);
        if (HASC) {
            float4 c = *reinterpret_cast<const float4*>(Cadd + (size_t)m * N + n);
            r.x += c.x; r.y += c.y; r.z += c.z; r.w += c.w;
        }
        *reinterpret_cast<float4*>(Out + (size_t)m * N + n) = r;
    }
}

// transpose + permute -> fp16 [2048 perm][ldd]; dup=1 writes copy at +K
__global__ void wsplit16_kernel(const float* __restrict__ src, int K,
                                __half* __restrict__ dst, int ldd, int dup) {
    __shared__ float sA[32][33];
    const int n0 = blockIdx.x * 32, k0 = blockIdx.y * 32;
    const int t = threadIdx.x;
    {
        int nl = t & 31, rr = t >> 5;
#pragma unroll
        for (int it = 0; it < 4; it++) {
            int kl = it * 8 + rr;
            sA[kl][nl] = src[(size_t)(k0 + kl) * NG + n0 + nl];
        }
    }
    __syncthreads();
    int nlo = t >> 3, ks = t & 7;
    int np = perm_col(n0 + nlo);
    union { __half h[4]; uint2 u; } H;
#pragma unroll
    for (int kk = 0; kk < 4; kk++)
        H.h[kk] = __float2half_rn(sA[ks * 4 + kk][nlo]);
    size_t base = (size_t)np * ldd + k0 + ks * 4;
    *reinterpret_cast<uint2*>(dst + base) = H.u;
    if (dup) *reinterpret_cast<uint2*>(dst + base + K) = H.u;
}

// x fp32 [m][256] -> x16 fp16 [m][512] = [x1|x2]
__global__ void xsplit_kernel(const float* __restrict__ x) {
    size_t i = (size_t)blockIdx.x * blockDim.x + threadIdx.x;  // float4 index
    float4 v = reinterpret_cast<const float4*>(x)[i];
    float f[4] = {v.x, v.y, v.z, v.w};
    union { __half h[4]; uint2 u; } H, L;
#pragma unroll
    for (int k = 0; k < 4; k++) {
        H.h[k] = __float2half_rn(f[k]);
        L.h[k] = __float2half_rn(f[k] - __half2float(H.h[k]));
    }
    size_t m = i >> 6, c = (i & 63) * 4;
    __half* row = g_x16 + m * 512 + c;
    *reinterpret_cast<uint2*>(row)       = H.u;
    *reinterpret_cast<uint2*>(row + 256) = L.u;
}

// ===================== P GEMM (HMMA fp16 2-term, time-major P out) ==========
__global__ __launch_bounds__(256)
void pgemm_mma(const __half* __restrict__ A, const __half* __restrict__ Bw, int Kc) {
    constexpr int BM = 128, BN = 128, WN_ = 4, MF = 4;
    __shared__ __half sA[2][BM][40];
    __shared__ __half sB[2][BN][40];
    const int tid = threadIdx.x, lane = tid & 31, w = tid >> 5;
    const int wn0 = (w % WN_) * 32, wm0 = (w / WN_) * 64;
    const int m0 = blockIdx.y * BM, n0 = blockIdx.x * BN;

    auto load_stage = [&](int s, int k0) {
#pragma unroll
        for (int i = 0; i < (BM + BN) * 4 / 256; i++) {
            int q = i * 256 + tid;
            const __half* src;
            uint32_t dst;
            if (q < BM * 4) {
                int r = q >> 2, c = q & 3;
                src = A + (size_t)(m0 + r) * Kc + k0 + c * 8;
                dst = smem_u32_of(&sA[s][r][c * 8]);
            } else {
                int q2 = q - BM * 4, r = q2 >> 2, c = q2 & 3;
                src = Bw + (size_t)(n0 + r) * Kc + k0 + c * 8;
                dst = smem_u32_of(&sB[s][r][c * 8]);
            }
            asm volatile("cp.async.cg.shared.global [%0], [%1], 16;" :: "r"(dst), "l"(src));
        }
        asm volatile("cp.async.commit_group;");
    };

    float acc[MF][4][4] = {};
    const int arow = (lane & 7) + ((lane >> 3) & 1) * 8;
    const int akm  = (lane >> 4) & 1;
    const int brow = lane & 7;
    const int bkm  = (lane >> 3) & 1;

    const int NIT = Kc >> 5;
    load_stage(0, 0);
    for (int it = 0; it < NIT; it++) {
        if (it + 1 < NIT) {
            load_stage((it + 1) & 1, (it + 1) * 32);
            asm volatile("cp.async.wait_group 1;");
        } else {
            asm volatile("cp.async.wait_group 0;");
        }
        __syncthreads();
        int s = it & 1;
#pragma unroll
        for (int ks = 0; ks < 2; ks++) {
            uint32_t aR[MF][4], bR[4][2];
#pragma unroll
            for (int ni = 0; ni < 4; ni++) {
                uint32_t ad = smem_u32_of(&sB[s][wn0 + ni * 8 + brow][ks * 16 + bkm * 8]);
                asm volatile("ldmatrix.sync.aligned.m8n8.x2.shared.b16 {%0,%1}, [%2];"
                             : "=r"(bR[ni][0]), "=r"(bR[ni][1]) : "r"(ad));
            }
#pragma unroll
            for (int mi = 0; mi < MF; mi++) {
                uint32_t ad = smem_u32_of(&sA[s][wm0 + mi * 16 + arow][ks * 16 + akm * 8]);
                asm volatile("ldmatrix.sync.aligned.m8n8.x4.shared.b16 {%0,%1,%2,%3}, [%4];"
                             : "=r"(aR[mi][0]), "=r"(aR[mi][1]), "=r"(aR[mi][2]), "=r"(aR[mi][3])
                             : "r"(ad));
            }
#pragma unroll
            for (int mi = 0; mi < MF; mi++)
#pragma unroll
                for (int ni = 0; ni < 4; ni++)
                    asm volatile(
                        "mma.sync.aligned.m16n8k16.row.col.f32.f16.f16.f32 "
                        "{%0,%1,%2,%3}, {%4,%5,%6,%7}, {%8,%9}, {%0,%1,%2,%3};"
                        : "+f"(acc[mi][ni][0]), "+f"(acc[mi][ni][1]),
                          "+f"(acc[mi][ni][2]), "+f"(acc[mi][ni][3])
                        : "r"(aR[mi][0]), "r"(aR[mi][1]), "r"(aR[mi][2]), "r"(aR[mi][3]),
                          "r"(bR[ni][0]), "r"(bR[ni][1]));
        }
        __syncthreads();
    }
#pragma unroll
    for (int mi = 0; mi < MF; mi++) {
#pragma unroll
        for (int half = 0; half < 2; half++) {
            int r = m0 + wm0 + mi * 16 + (lane >> 2) + half * 8;
            size_t dr = (size_t)(r & (NL - 1)) * NB + (size_t)(r >> 7);
#pragma unroll
            for (int ni = 0; ni < 4; ni++) {
                int col = n0 + wn0 + ni * 8 + (lane & 3) * 2;
                *reinterpret_cast<float2*>(&g_P[dr * NG + col]) =
                    make_float2(acc[mi][ni][half * 2 + 0] + g_bvp[col],
                                acc[mi][ni][half * 2 + 1] + g_bvp[col + 1]);
            }
        }
    }
}

// ===================== persistent scan kernel ===============================
// fp16 1-term: gates_rec = h @ W1 (h fp16, W1 = fp16(W') resident in SMEM).
// A per step: [64 b][512] fp16; 4 chunks of 128 k, ALL issued up front.
static constexpr int SBP = 520;                        // halves (1040 B pitch)
static constexpr int SAP = 136;                        // halves (272 B pitch)
static constexpr int SA_STAGE = 64 * SAP;
static constexpr int SCAN_SMEM = (64 * SBP + 4 * SA_STAGE) * 2;   // 136,192 B

__device__ __forceinline__ void wait_grp(int n) {
    switch (n) {
        case 0: asm volatile("cp.async.wait_group 0;" ::: "memory"); break;
        case 1: asm volatile("cp.async.wait_group 1;" ::: "memory"); break;
        case 2: asm volatile("cp.async.wait_group 2;" ::: "memory"); break;
        default: asm volatile("cp.async.wait_group 3;" ::: "memory"); break;
    }
}

__global__ __launch_bounds__(256)
void scan_kernel(float* __restrict__ out) {
    extern __shared__ __half sm16[];
    __half* sB = sm16;                                // [64][520]
    __half* sA = sm16 + 64 * SBP;                     // [4][64][136]
    const int tid = threadIdx.x, lane = tid & 31, w = tid >> 5;
    const int n0 = blockIdx.x * 64, m0 = blockIdx.y * 64, grp = blockIdx.y;
    const int wn0 = (w & 1) * 32, wm0 = (w >> 1) * 16;

    // ---- resident B tile: W1 rows n0..n0+63, 512 cols ----------------------
#pragma unroll
    for (int i = 0; i < 16; i++) {
        int q = i * 256 + tid;                        // 4096 16B-chunks
        int r = q >> 6, cc = q & 63;
        asm volatile("cp.async.cg.shared.global [%0], [%1], 16;"
                     :: "r"(smem_u32_of(sB + r * SBP + cc * 8)),
                        "l"(g_Wp16 + (size_t)(n0 + r) * NH + cc * 8));
    }
    asm volatile("cp.async.commit_group;");
    asm volatile("cp.async.wait_group 0;");
    __syncthreads();

    const int arow = (lane & 7) + ((lane >> 3) & 1) * 8;
    const int akm  = (lane >> 4) & 1;
    const int browB = ((lane >> 4) & 1) * 8 + (lane & 7);
    const int bkmB  = (lane >> 3) & 1;
    const int p0 = (lane & 3) * 2;
    const int j = ((n0 + wn0) >> 5) * 8 + p0;         // hidden unit (even)

    for (int t = 0; t < NL; t++) {
        const int par = t & 1;
        const __half* hsrc = g_h16[par];

        // issue ALL 4 A chunks (16 KB each) immediately
#pragma unroll
        for (int c = 0; c < 4; c++) {
#pragma unroll
            for (int i = 0; i < 4; i++) {
                int q = i * 256 + tid;
                int r = q >> 4, cc = q & 15;
                asm volatile("cp.async.cg.shared.global [%0], [%1], 16;"
                             :: "r"(smem_u32_of(sA + c * SA_STAGE + r * SAP + cc * 8)),
                                "l"(hsrc + (size_t)(m0 + r) * NH + c * 128 + cc * 8));
            }
            asm volatile("cp.async.commit_group;");
        }

        // P prefetch (DRAM; overlaps with chunk0 latency)
        float2 pv[2][4];
        {
            const float* Pt = g_P + (size_t)t * NB * NG;
#pragma unroll
            for (int half = 0; half < 2; half++) {
                int b = m0 + wm0 + (lane >> 2) + half * 8;
#pragma unroll
                for (int ni = 0; ni < 4; ni++)
                    pv[half][ni] = __ldg(reinterpret_cast<const float2*>(
                        Pt + (size_t)b * NG + n0 + wn0 + ni * 8 + p0));
            }
        }

        float acc[4][4] = {};
#pragma unroll
        for (int c = 0; c < 4; c++) {
            wait_grp(3 - c);
            __syncthreads();
            const __half* As = sA + c * SA_STAGE;
            const int kb = c * 128;
#pragma unroll
            for (int ks = 0; ks < 8; ks++) {
                uint32_t aR[4];
                asm volatile("ldmatrix.sync.aligned.m8n8.x4.shared.b16 {%0,%1,%2,%3}, [%4];"
                             : "=r"(aR[0]), "=r"(aR[1]), "=r"(aR[2]), "=r"(aR[3])
                             : "r"(smem_u32_of(As + (wm0 + arow) * SAP + ks * 16 + akm * 8)));
#pragma unroll
                for (int p = 0; p < 2; p++) {
                    uint32_t b4[4];
                    asm volatile("ldmatrix.sync.aligned.m8n8.x4.shared.b16 {%0,%1,%2,%3}, [%4];"
                                 : "=r"(b4[0]), "=r"(b4[1]), "=r"(b4[2]), "=r"(b4[3])
                                 : "r"(smem_u32_of(sB + (wn0 + p * 16 + browB) * SBP
                                                   + kb + ks * 16 + bkmB * 8)));
                    asm volatile(
                        "mma.sync.aligned.m16n8k16.row.col.f32.f16.f16.f32 "
                        "{%0,%1,%2,%3}, {%4,%5,%6,%7}, {%8,%9}, {%0,%1,%2,%3};"
                        : "+f"(acc[2 * p][0]), "+f"(acc[2 * p][1]),
                          "+f"(acc[2 * p][2]), "+f"(acc[2 * p][3])
                        : "r"(aR[0]), "r"(aR[1]), "r"(aR[2]), "r"(aR[3]),
                          "r"(b4[0]), "r"(b4[1]));
                    asm volatile(
                        "mma.sync.aligned.m16n8k16.row.col.f32.f16.f16.f32 "
                        "{%0,%1,%2,%3}, {%4,%5,%6,%7}, {%8,%9}, {%0,%1,%2,%3};"
                        : "+f"(acc[2 * p + 1][0]), "+f"(acc[2 * p + 1][1]),
                          "+f"(acc[2 * p + 1][2]), "+f"(acc[2 * p + 1][3])
                        : "r"(aR[0]), "r"(aR[1]), "r"(aR[2]), "r"(aR[3]),
                          "r"(b4[2]), "r"(b4[3]));
                }
            }
        }

        // ---- fused LSTM pointwise epilogue ---------------------------------
        __half* hdst = g_h16[par ^ 1];
#pragma unroll
        for (int half = 0; half < 2; half++) {
            int b = m0 + wm0 + (lane >> 2) + half * 8;
            float2 cold = *reinterpret_cast<float2*>(&g_Cst[(size_t)b * NH + j]);
            float hn[2], cn[2];
#pragma unroll
            for (int e = 0; e < 2; e++) {
                int a = half * 2 + e;
                float iv = acc[0][a] + (e ? pv[half][0].y : pv[half][0].x);
                float fv = acc[1][a] + (e ? pv[half][1].y : pv[half][1].x);
                float gv = acc[2][a] + (e ? pv[half][2].y : pv[half][2].x);
                float ov = acc[3][a] + (e ? pv[half][3].y : pv[half][3].x);
                float si = 1.f / (1.f + expf(-iv));
                float sf = 1.f / (1.f + expf(-fv));
                float so = 1.f / (1.f + expf(-ov));
                float tg = tanhf(gv);
                float Cn = sf * (e ? cold.y : cold.x) + si * tg;
                cn[e] = Cn;
                hn[e] = so * tanhf(Cn);
            }
            *reinterpret_cast<float2*>(&g_Cst[(size_t)b * NH + j]) = make_float2(cn[0], cn[1]);
            size_t o = (size_t)b * (NL * NH) + (size_t)t * NH + j;
            *reinterpret_cast<float2*>(&out[o]) = make_float2(hn[0], hn[1]);
            *reinterpret_cast<float2*>(&out[o + (size_t)NB * NL * NH]) = make_float2(cn[0], cn[1]);
            *reinterpret_cast<__half2*>(hdst + (size_t)b * NH + j) =
                __halves2half2(__float2half_rn(hn[0]), __float2half_rn(hn[1]));
        }

        // ---- per-m-group barrier ------------------------------------------
        __threadfence();
        __syncthreads();
        if (tid == 0) {
            atomicAdd(&g_bar[grp], 1);
            int target = 32 * (t + 1);
            while (*((volatile int*)&g_bar[grp]) < target) __nanosleep(32);
        }
        __syncthreads();
    }
}

// ===================== x_tilde ==============================================
__global__ void xtilde_kernel(const float* __restrict__ x, const float* __restrict__ Wa,
                              const float* __restrict__ ba, float* __restrict__ out) {
    __shared__ float red[NC];
    __shared__ float s_wa[NL];
    int b = blockIdx.x, c = threadIdx.x;
    if (c < NL) s_wa[c] = Wa[2 * NH + c];
    __syncthreads();
    const float* xb = x + (size_t)b * NL * NC;
    float s = ba[0];
#pragma unroll 4
    for (int l = 0; l < NL; l++) s = fmaf(xb[(size_t)l * NC + c], s_wa[l], s);
    red[c] = s; __syncthreads();
    for (int o = NC / 2; o > 0; o >>= 1) { if (c < o) red[c] = fmaxf(red[c], red[c + o]); __syncthreads(); }
    float mx = red[0]; __syncthreads();
    float e = expf(s - mx);
    red[c] = e; __syncthreads();
    for (int o = NC / 2; o > 0; o >>= 1) { if (c < o) red[c] += red[c + o]; __syncthreads(); }
    float alpha = e / red[0];
    float* ob = out + (size_t)b * NL * NC;
#pragma unroll 4
    for (int l = 0; l < NL; l++) ob[(size_t)l * NC + c] = alpha * xb[(size_t)l * NC + c];
}

// ===================== host =================================================
extern "C" void kernel_launch(void* const* d_in, const int* in_sizes, int n_in,
                              void* d_out, int out_size) {
    const float* x   = (const float*)d_in[0];
    const float* Wih = (const float*)d_in[1];
    const float* bih = (const float*)d_in[2];
    const float* Wmx = (const float*)d_in[3];
    const float* bmx = (const float*)d_in[4];
    const float* Wmh = (const float*)d_in[5];
    const float* bmh = (const float*)d_in[6];
    const float* Whm = (const float*)d_in[7];
    const float* bhm = (const float*)d_in[8];
    const float* Wa  = (const float*)d_in[9];
    const float* ba  = (const float*)d_in[10];
    float* out = (float*)d_out;

    float *pWp, *pWb;
    __half *pWp16, *pWb16, *pX16;
    cudaGetSymbolAddress((void**)&pWp,   g_Wp);
    cudaGetSymbolAddress((void**)&pWb,   g_Wb);
    cudaGetSymbolAddress((void**)&pWp16, g_Wp16);
    cudaGetSymbolAddress((void**)&pWb16, g_Wb16);
    cudaGetSymbolAddress((void**)&pX16,  g_x16);

    cudaFuncSetAttribute(scan_kernel, cudaFuncAttributeMaxDynamicSharedMemorySize, SCAN_SMEM);

    init_state_kernel<<<(NB * NH + 255) / 256, 256>>>();

    // folded weights (fp32 SIMT — small)
    gemm64<false><<<dim3(NG / 64, NH / 64), 256>>>(Wmh, Whm, nullptr, pWp, NH, NG, NH);
    gemm64<true ><<<dim3(NG / 64, NC / 64), 256>>>(Wmx, Whm, Wih, pWb, NC, NG, NH);
    bvec_kernel<<<dim3(8, 8), 256>>>(bih, bhm, bmx, bmh, Whm);

    // weight / x conversions to fp16
    wsplit16_kernel<<<dim3(NG / 32, NH / 32), 256>>>(pWp, NH, pWp16, NH, 0);
    wsplit16_kernel<<<dim3(NG / 32, NC / 32), 256>>>(pWb, NC, pWb16, 512, 1);
    xsplit_kernel<<<(NB * NL * NC / 4) / 256, 256>>>(x);

    // P = x @ Wbig + bias  (HMMA fp16 2-term, Kc=512, time-major output)
    pgemm_mma<<<dim3(NG / 128, (NB * NL) / 128), 256>>>(pX16, pWb16, 512);

    // x_tilde (softmax over c is time-invariant)
    xtilde_kernel<<<NB, 256>>>(x, Wa, ba, out + (size_t)2 * NB * NL * NH);

    // persistent fused scan: all 128 steps in ONE launch (fp16 1-term)
    scan_kernel<<<dim3(32, 4), 256, SCAN_SMEM>>>(out);
}